// round 1
// baseline (speedup 1.0000x reference)
#include <cuda_runtime.h>

#define Bn 8
#define Cc 512
#define CQ 64
#define Hh 128
#define Ww 128
#define HW (Hh*Ww)   // 16384

// Scratch for q/k/v conv outputs (layout identical to reference conv output [B][O][H][W])
__device__ float g_q[(size_t)Bn*CQ*HW];          // 33.5 MB
__device__ float g_k[(size_t)Bn*CQ*HW];          // 33.5 MB
__device__ float g_v[(size_t)Bn*Cc*HW];          // 268 MB

// ---------------------------------------------------------------------------
// Kernel 1: QKV GEMM.  For each batch b: out[oc][s] = sum_ch W[oc][ch] x[b][ch][s] + bias
// oc tile of 64 never straddles q/k/v boundary (boundaries at 64,128).
// Tile: 64 oc x 64 spatial x K-chunk 16, 256 threads, 4x4 microtile.
// ---------------------------------------------------------------------------
__global__ void __launch_bounds__(256, 1) qkv_kernel(
    const float* __restrict__ x,
    const float* __restrict__ Wq, const float* __restrict__ bq,
    const float* __restrict__ Wk, const float* __restrict__ bk,
    const float* __restrict__ Wv, const float* __restrict__ bv)
{
    const int b   = blockIdx.z;
    const int oc0 = blockIdx.y * 64;
    const int s0  = blockIdx.x * 64;

    const float* Wp; const float* bp; float* outp; int ocbase;
    if (oc0 < 64)        { Wp = Wq; bp = bq; outp = g_q + (size_t)b*CQ*HW; ocbase = oc0; }
    else if (oc0 < 128)  { Wp = Wk; bp = bk; outp = g_k + (size_t)b*CQ*HW; ocbase = oc0 - 64; }
    else                 { Wp = Wv; bp = bv; outp = g_v + (size_t)b*Cc*HW; ocbase = oc0 - 128; }

    __shared__ float ws[16][68];   // ws[k][oc]
    __shared__ float xs[16][68];   // xs[k][sp]

    const float* xb = x + (size_t)b*Cc*HW + s0;

    const int tid = threadIdx.x;
    const int tx = tid & 15;   // spatial group
    const int ty = tid >> 4;   // oc group
    float acc[4][4] = {};

    for (int kc = 0; kc < Cc; kc += 16) {
        // load weight tile (rows ocbase..+63, cols kc..+15), transposed into ws[k][oc]
        {
            int oc = tid >> 2;
            int k4 = (tid & 3) << 2;
            float4 wv4 = *(const float4*)(Wp + (size_t)(ocbase + oc)*Cc + kc + k4);
            ws[k4+0][oc] = wv4.x; ws[k4+1][oc] = wv4.y;
            ws[k4+2][oc] = wv4.z; ws[k4+3][oc] = wv4.w;
        }
        // load x tile: xs[k][sp]
        {
            int k  = tid >> 4;
            int sp = (tid & 15) << 2;
            *(float4*)&xs[k][sp] = *(const float4*)(xb + (size_t)(kc + k)*HW + sp);
        }
        __syncthreads();
        #pragma unroll
        for (int k = 0; k < 16; k++) {
            float a[4], bb[4];
            *(float4*)a  = *(const float4*)&ws[k][ty << 2];
            *(float4*)bb = *(const float4*)&xs[k][tx << 2];
            #pragma unroll
            for (int i = 0; i < 4; i++)
                #pragma unroll
                for (int j = 0; j < 4; j++)
                    acc[i][j] += a[i] * bb[j];
        }
        __syncthreads();
    }

    #pragma unroll
    for (int i = 0; i < 4; i++) {
        int oc = ocbase + (ty << 2) + i;
        float bias = bp[oc];
        float4 r = make_float4(acc[i][0] + bias, acc[i][1] + bias,
                               acc[i][2] + bias, acc[i][3] + bias);
        *(float4*)(outp + (size_t)oc*HW + s0 + (tx << 2)) = r;
    }
}

// ---------------------------------------------------------------------------
// Kernel 2: per-(b,h) row attention. One CTA per (b,h), 1024 CTAs, 256 threads.
// query_row[i][c] = qflat[i*64+c]  where qflat[j] = q[b][j>>7][h][j&127]
// key_row [c][m] = kflat[c*128+m] where kflat[j] = k[b][j&63][h][j>>6]
// energy = query_row @ key_row; softmax rows; out[i][c] = sum_m attn[i][m]*v[b][c][h][m]
// final[b][c][h][i] = gamma*out[i][c] + x[b][c][h][i]
// ---------------------------------------------------------------------------
#define SQ_STRIDE 68    // qv rows of 64 + pad
#define SK_STRIDE 132   // kv rows of 128 + pad (float4-aligned)
#define SA_STRIDE 133   // attn rows of 128 + pad (conflict-free column reads)
#define OFF_SK (128*SQ_STRIDE)                 // 8704
#define OFF_SA (OFF_SK + 64*SK_STRIDE)         // 17152
#define SMEM_FLOATS (OFF_SA + 128*SA_STRIDE)   // 34176
#define SMEM_BYTES (SMEM_FLOATS*4)             // 136704

__global__ void __launch_bounds__(256, 1) attn_kernel(
    const float* __restrict__ x,
    const float* __restrict__ gamma_p,
    float* __restrict__ outp)
{
    extern __shared__ float smem[];
    float* sq = smem;             // qv[128][68]  : query_row
    float* sk = smem + OFF_SK;    // kv[64][132]  : key_row
    float* sa = smem + OFF_SA;    // attn[128][133]
    float* vs = smem;             // v chunk [64][132], reuses sq region after softmax

    const int bh = blockIdx.x;
    const int b  = bh >> 7;
    const int h  = bh & 127;
    const int tid = threadIdx.x;

    // ---- load q slab into query_row layout ----
    for (int idx = tid * 4; idx < CQ * Ww; idx += 256 * 4) {
        int cq = idx >> 7;
        int w0 = idx & 127;
        float4 val = *(const float4*)(g_q + ((size_t)(b*CQ + cq)*Hh + h)*Ww + w0);
        int i  = idx >> 6;        // idx = cq*128 + w0 is the flat query index
        int c0 = idx & 63;
        *(float4*)&sq[i*SQ_STRIDE + c0] = val;
    }
    // ---- load k slab into key_row layout (scrambled scatter) ----
    for (int idx = tid; idx < CQ * Ww; idx += 256) {
        int cq = idx >> 7;
        int w  = idx & 127;
        float val = g_k[((size_t)(b*CQ + cq)*Hh + h)*Ww + w];
        int j = w*64 + cq;        // flat key_row index
        sk[(j >> 7)*SK_STRIDE + (j & 127)] = val;
    }
    __syncthreads();

    // ---- energy GEMM: [128 x 64] @ [64 x 128], thread = 8x8 microtile ----
    {
        const int tm = tid >> 4;   // i group
        const int tn = tid & 15;   // m group
        float e[8][8] = {};
        for (int c = 0; c < 64; c++) {
            float qr[8], kr[8];
            #pragma unroll
            for (int ii = 0; ii < 8; ii++) qr[ii] = sq[(tm*8 + ii)*SQ_STRIDE + c];
            *(float4*)&kr[0] = *(const float4*)&sk[c*SK_STRIDE + tn*8];
            *(float4*)&kr[4] = *(const float4*)&sk[c*SK_STRIDE + tn*8 + 4];
            #pragma unroll
            for (int ii = 0; ii < 8; ii++)
                #pragma unroll
                for (int jj = 0; jj < 8; jj++)
                    e[ii][jj] += qr[ii] * kr[jj];
        }
        #pragma unroll
        for (int ii = 0; ii < 8; ii++)
            #pragma unroll
            for (int jj = 0; jj < 8; jj++)
                sa[(tm*8 + ii)*SA_STRIDE + tn*8 + jj] = e[ii][jj];
    }
    __syncthreads();

    // ---- softmax per row (128 rows, 1 thread each) ----
    if (tid < 128) {
        float* row = &sa[tid*SA_STRIDE];
        float mx = -1e30f;
        #pragma unroll 4
        for (int m = 0; m < 128; m++) mx = fmaxf(mx, row[m]);
        float s = 0.f;
        #pragma unroll 4
        for (int m = 0; m < 128; m++) { float ev = __expf(row[m] - mx); row[m] = ev; s += ev; }
        float inv = 1.f / s;
        #pragma unroll 4
        for (int m = 0; m < 128; m++) row[m] *= inv;
    }

    // ---- out GEMM: attn[128x128] @ v_slab^T, chunks of 64 output channels ----
    const float gma = __ldg(gamma_p);
    const int lane = tid & 31;
    const int tw   = tid >> 5;

    for (int cc = 0; cc < Cc; cc += 64) {
        __syncthreads();   // protect vs region (prev compute / softmax)
        for (int idx = tid * 4; idx < 64 * Ww; idx += 256 * 4) {
            int c  = idx >> 7;
            int m0 = idx & 127;
            float4 val = *(const float4*)(g_v + ((size_t)(b*Cc + cc + c)*Hh + h)*Ww + m0);
            *(float4*)&vs[c*SK_STRIDE + m0] = val;
        }
        __syncthreads();

        float o[4][8] = {};
        for (int m = 0; m < 128; m++) {
            float a0 = sa[(lane      )*SA_STRIDE + m];
            float a1 = sa[(lane + 32 )*SA_STRIDE + m];
            float a2 = sa[(lane + 64 )*SA_STRIDE + m];
            float a3 = sa[(lane + 96 )*SA_STRIDE + m];
            #pragma unroll
            for (int j = 0; j < 8; j++) {
                float vv = vs[(tw*8 + j)*SK_STRIDE + m];
                o[0][j] += a0 * vv;
                o[1][j] += a1 * vv;
                o[2][j] += a2 * vv;
                o[3][j] += a3 * vv;
            }
        }

        #pragma unroll
        for (int ii = 0; ii < 4; ii++) {
            int i = lane + 32*ii;
            #pragma unroll
            for (int j = 0; j < 8; j++) {
                int c = cc + tw*8 + j;
                size_t idx = ((size_t)(b*Cc + c)*Hh + h)*Ww + i;
                outp[idx] = gma * o[ii][j] + x[idx];
            }
        }
    }
}

// ---------------------------------------------------------------------------
extern "C" void kernel_launch(void* const* d_in, const int* in_sizes, int n_in,
                              void* d_out, int out_size)
{
    (void)in_sizes; (void)n_in; (void)out_size;
    const float* x     = (const float*)d_in[0];
    const float* Wq    = (const float*)d_in[1];
    const float* bq    = (const float*)d_in[2];
    const float* Wk    = (const float*)d_in[3];
    const float* bk    = (const float*)d_in[4];
    const float* Wv    = (const float*)d_in[5];
    const float* bv    = (const float*)d_in[6];
    const float* gamma = (const float*)d_in[7];
    float* out = (float*)d_out;

    dim3 g1(HW/64, 640/64, Bn);
    qkv_kernel<<<g1, 256>>>(x, Wq, bq, Wk, bk, Wv, bv);

    cudaFuncSetAttribute(attn_kernel, cudaFuncAttributeMaxDynamicSharedMemorySize, SMEM_BYTES);
    attn_kernel<<<Bn*Hh, 256, SMEM_BYTES>>>(x, gamma, out);
}

// round 3
// speedup vs baseline: 1.6864x; 1.6864x over previous
#include <cuda_runtime.h>
#include <cuda_bf16.h>
#include <cstdint>

#define Bn 8
#define Cc 512
#define CQ 64
#define Hh 128
#define Ww 128
#define HW (Hh*Ww)   // 16384

// ---------------------------------------------------------------------------
// Device scratch
// ---------------------------------------------------------------------------
__device__ float g_q[(size_t)Bn*CQ*HW];
__device__ float g_k[(size_t)Bn*CQ*HW];
__device__ float g_v[(size_t)Bn*Cc*HW];
__device__ __nv_bfloat16 g_xt_hi[(size_t)Bn*HW*Cc];   // xT[b][s][ch]
__device__ __nv_bfloat16 g_xt_lo[(size_t)Bn*HW*Cc];
__device__ __nv_bfloat16 g_w_hi[640*Cc];              // rows: q(0..63), k(64..127), v(128..639)
__device__ __nv_bfloat16 g_w_lo[640*Cc];
__device__ float g_bias[640];

// ---------------------------------------------------------------------------
// helpers
// ---------------------------------------------------------------------------
__device__ __forceinline__ uint32_t smem_u32(const void* p) {
    uint32_t a;
    asm("{ .reg .u64 t; cvta.to.shared.u64 t, %1; cvt.u32.u64 %0, t; }" : "=r"(a) : "l"(p));
    return a;
}
__device__ __forceinline__ void cp16(uint32_t dst, const void* src) {
    asm volatile("cp.async.cg.shared.global [%0], [%1], 16;" :: "r"(dst), "l"(src));
}
#define CP_COMMIT()     asm volatile("cp.async.commit_group;" ::: "memory")
#define CP_WAIT_GROUP(n) asm volatile("cp.async.wait_group %0;" :: "n"(n) : "memory")

__device__ __forceinline__ void mma16816(float c[4], uint32_t a0, uint32_t a1, uint32_t a2, uint32_t a3,
                                         uint32_t b0, uint32_t b1) {
    asm volatile("mma.sync.aligned.m16n8k16.row.col.f32.bf16.bf16.f32 "
                 "{%0,%1,%2,%3}, {%4,%5,%6,%7}, {%8,%9}, {%0,%1,%2,%3};"
                 : "+f"(c[0]), "+f"(c[1]), "+f"(c[2]), "+f"(c[3])
                 : "r"(a0), "r"(a1), "r"(a2), "r"(a3), "r"(b0), "r"(b1));
}

// ---------------------------------------------------------------------------
// Prep: W -> bf16 hi/lo (concat rows), bias concat
// ---------------------------------------------------------------------------
__global__ void prep_w(const float* __restrict__ Wq, const float* __restrict__ bq,
                       const float* __restrict__ Wk, const float* __restrict__ bk,
                       const float* __restrict__ Wv, const float* __restrict__ bv)
{
    int r = blockIdx.x;   // 0..639
    const float* src; float bias;
    if (r < 64)       { src = Wq + (size_t)r*Cc;        bias = bq[r]; }
    else if (r < 128) { src = Wk + (size_t)(r-64)*Cc;   bias = bk[r-64]; }
    else              { src = Wv + (size_t)(r-128)*Cc;  bias = bv[r-128]; }
    if (threadIdx.x == 0) g_bias[r] = bias;
    for (int c = threadIdx.x; c < Cc; c += blockDim.x) {
        float v = src[c];
        __nv_bfloat16 h = __float2bfloat16(v);
        float lo = v - __bfloat162float(h);
        g_w_hi[(size_t)r*Cc + c] = h;
        g_w_lo[(size_t)r*Cc + c] = __float2bfloat16(lo);
    }
}

// ---------------------------------------------------------------------------
// Prep: x[b][ch][s] -> xT hi/lo [b][s][ch]  (64x64 tile transpose)
// ---------------------------------------------------------------------------
__global__ void __launch_bounds__(256) prep_xt(const float* __restrict__ x)
{
    __shared__ float st[64*65];
    const int b = blockIdx.z, ch0 = blockIdx.y * 64, s0 = blockIdx.x * 64;
    const float* xb = x + ((size_t)b*Cc + ch0)*HW + s0;
    for (int i = threadIdx.x; i < 64*64; i += 256) {
        int ch = i >> 6, s = i & 63;
        st[ch*65 + s] = xb[(size_t)ch*HW + s];
    }
    __syncthreads();
    for (int u = threadIdx.x; u < 512; u += 256) {
        int s = u >> 3, c8 = (u & 7) * 8;
        uint32_t hi[4], lo[4];
        #pragma unroll
        for (int j = 0; j < 4; j++) {
            float a = st[(c8 + 2*j    )*65 + s];
            float c = st[(c8 + 2*j + 1)*65 + s];
            __nv_bfloat16 ah = __float2bfloat16(a), ch_ = __float2bfloat16(c);
            __nv_bfloat16 al = __float2bfloat16(a - __bfloat162float(ah));
            __nv_bfloat16 cl = __float2bfloat16(c - __bfloat162float(ch_));
            hi[j] = (uint32_t)__bfloat16_as_ushort(ah) | ((uint32_t)__bfloat16_as_ushort(ch_) << 16);
            lo[j] = (uint32_t)__bfloat16_as_ushort(al) | ((uint32_t)__bfloat16_as_ushort(cl) << 16);
        }
        size_t off = ((size_t)(b*HW + s0 + s))*Cc + ch0 + c8;
        *(uint4*)(g_xt_hi + off) = make_uint4(hi[0], hi[1], hi[2], hi[3]);
        *(uint4*)(g_xt_lo + off) = make_uint4(lo[0], lo[1], lo[2], lo[3]);
    }
}

// ---------------------------------------------------------------------------
// QKV GEMM via mma.sync bf16 (3-term hi/lo split).
// D[m][n] = sum_k W[m][k] * xT[b][n][k],   m0 tile 128, n0 tile 128, k chunks 32.
// smem stage: Ah | Al | Bh | Bl, each 128 rows x 80B (64B data + 16B pad).
// ---------------------------------------------------------------------------
#define ROWB 80
#define SEG  10240            // 128*80
#define STAGE (4*SEG)         // 40960
#define NSTAGE 3
#define SM_GEMM (NSTAGE*STAGE)  // 122880

__device__ __forceinline__ void load_chunk(uint32_t sb, int tid, int k0, int m0, size_t bofs)
{
    const __nv_bfloat16* srcs[4] = {
        g_w_hi + (size_t)m0*Cc + k0,
        g_w_lo + (size_t)m0*Cc + k0,
        g_xt_hi + bofs + k0,
        g_xt_lo + bofs + k0 };
    #pragma unroll
    for (int i = tid; i < 2048; i += 256) {
        int seg = i >> 9;
        int r = (i & 511) >> 2, u = i & 3;
        cp16(sb + seg*SEG + r*ROWB + u*16, srcs[seg] + (size_t)r*Cc + u*8);
    }
    CP_COMMIT();
}

__global__ void __launch_bounds__(256, 1) qkv_gemm()
{
    extern __shared__ char smem[];
    const uint32_t sbase = smem_u32(smem);
    const int tid = threadIdx.x, wid = tid >> 5, lane = tid & 31;
    const int g = lane >> 2, q = lane & 3;
    const int m0 = blockIdx.x * 128;          // m fastest -> B-tile L2 reuse
    const int n0 = blockIdx.y * 128;
    const int b  = blockIdx.z;
    const size_t bofs = ((size_t)b*HW + n0)*Cc;

    const int wm = wid & 1;      // 2 warps in m
    const int wn = wid >> 1;     // 4 warps in n

    float acc[4][4][4];
    #pragma unroll
    for (int i = 0; i < 4; i++)
        #pragma unroll
        for (int j = 0; j < 4; j++)
            #pragma unroll
            for (int e = 0; e < 4; e++) acc[i][j][e] = 0.f;

    load_chunk(sbase, tid, 0, m0, bofs);
    load_chunk(sbase + STAGE, tid, 32, m0, bofs);

    for (int c = 0; c < 16; c++) {
        CP_WAIT_GROUP(1);
        __syncthreads();
        if (c + 2 < 16)
            load_chunk(sbase + ((c+2) % NSTAGE)*STAGE, tid, (c+2)*32, m0, bofs);

        const uint32_t sb = sbase + (c % NSTAGE)*STAGE;
        #pragma unroll
        for (int ks = 0; ks < 2; ks++) {
            uint32_t ah[4][4], al[4][4], bh[4][2], bl[4][2];
            #pragma unroll
            for (int tm = 0; tm < 4; tm++) {
                uint32_t ra = sb + (wm*64 + tm*16 + g)*ROWB + ks*32 + q*4;
                ah[tm][0] = *(const uint32_t*)(smem + (ra - sbase));
                ah[tm][1] = *(const uint32_t*)(smem + (ra + 8*ROWB - sbase));
                ah[tm][2] = *(const uint32_t*)(smem + (ra + 16 - sbase));
                ah[tm][3] = *(const uint32_t*)(smem + (ra + 8*ROWB + 16 - sbase));
                al[tm][0] = *(const uint32_t*)(smem + (ra + SEG - sbase));
                al[tm][1] = *(const uint32_t*)(smem + (ra + SEG + 8*ROWB - sbase));
                al[tm][2] = *(const uint32_t*)(smem + (ra + SEG + 16 - sbase));
                al[tm][3] = *(const uint32_t*)(smem + (ra + SEG + 8*ROWB + 16 - sbase));
            }
            #pragma unroll
            for (int tn = 0; tn < 4; tn++) {
                uint32_t rb = sb + 2*SEG + (wn*32 + tn*8 + g)*ROWB + ks*32 + q*4;
                bh[tn][0] = *(const uint32_t*)(smem + (rb - sbase));
                bh[tn][1] = *(const uint32_t*)(smem + (rb + 16 - sbase));
                bl[tn][0] = *(const uint32_t*)(smem + (rb + SEG - sbase));
                bl[tn][1] = *(const uint32_t*)(smem + (rb + SEG + 16 - sbase));
            }
            #pragma unroll
            for (int tm = 0; tm < 4; tm++)
                #pragma unroll
                for (int tn = 0; tn < 4; tn++) {
                    mma16816(acc[tm][tn], ah[tm][0], ah[tm][1], ah[tm][2], ah[tm][3], bh[tn][0], bh[tn][1]);
                    mma16816(acc[tm][tn], ah[tm][0], ah[tm][1], ah[tm][2], ah[tm][3], bl[tn][0], bl[tn][1]);
                    mma16816(acc[tm][tn], al[tm][0], al[tm][1], al[tm][2], al[tm][3], bh[tn][0], bh[tn][1]);
                }
        }
        __syncthreads();
    }

    // Epilogue: direct float2 stores with bias, routed to g_q/g_k/g_v
    #pragma unroll
    for (int tm = 0; tm < 4; tm++) {
        int mrow = m0 + wm*64 + tm*16 + g;
        float bias0 = g_bias[mrow];
        float bias1 = g_bias[mrow + 8];
        #pragma unroll
        for (int tn = 0; tn < 4; tn++) {
            int n = n0 + wn*32 + tn*8 + q*2;
            float* d0;
            float* d1;
            {
                int oc = mrow;
                if (oc < 64)       d0 = g_q + ((size_t)b*CQ + oc)*HW;
                else if (oc < 128) d0 = g_k + ((size_t)b*CQ + oc - 64)*HW;
                else               d0 = g_v + ((size_t)b*Cc + oc - 128)*HW;
                oc = mrow + 8;
                if (oc < 64)       d1 = g_q + ((size_t)b*CQ + oc)*HW;
                else if (oc < 128) d1 = g_k + ((size_t)b*CQ + oc - 64)*HW;
                else               d1 = g_v + ((size_t)b*Cc + oc - 128)*HW;
            }
            float2 v0 = make_float2(acc[tm][tn][0] + bias0, acc[tm][tn][1] + bias0);
            float2 v1 = make_float2(acc[tm][tn][2] + bias1, acc[tm][tn][3] + bias1);
            *(float2*)(d0 + n) = v0;
            *(float2*)(d1 + n) = v1;
        }
    }
}

// ---------------------------------------------------------------------------
// Attention kernel (unchanged, proven correct in R1)
// ---------------------------------------------------------------------------
#define SQ_STRIDE 68
#define SK_STRIDE 132
#define SA_STRIDE 133
#define OFF_SK (128*SQ_STRIDE)
#define OFF_SA (OFF_SK + 64*SK_STRIDE)
#define SMEM_FLOATS (OFF_SA + 128*SA_STRIDE)
#define SMEM_BYTES (SMEM_FLOATS*4)

__global__ void __launch_bounds__(256, 1) attn_kernel(
    const float* __restrict__ x,
    const float* __restrict__ gamma_p,
    float* __restrict__ outp)
{
    extern __shared__ float smemf[];
    float* sq = smemf;
    float* sk = smemf + OFF_SK;
    float* sa = smemf + OFF_SA;
    float* vs = smemf;

    const int bh = blockIdx.x;
    const int b  = bh >> 7;
    const int h  = bh & 127;
    const int tid = threadIdx.x;

    for (int idx = tid * 4; idx < CQ * Ww; idx += 256 * 4) {
        int cq = idx >> 7;
        int w0 = idx & 127;
        float4 val = *(const float4*)(g_q + ((size_t)(b*CQ + cq)*Hh + h)*Ww + w0);
        int i  = idx >> 6;
        int c0 = idx & 63;
        *(float4*)&sq[i*SQ_STRIDE + c0] = val;
    }
    for (int idx = tid; idx < CQ * Ww; idx += 256) {
        int cq = idx >> 7;
        int w  = idx & 127;
        float val = g_k[((size_t)(b*CQ + cq)*Hh + h)*Ww + w];
        int j = w*64 + cq;
        sk[(j >> 7)*SK_STRIDE + (j & 127)] = val;
    }
    __syncthreads();

    {
        const int tm = tid >> 4;
        const int tn = tid & 15;
        float e[8][8] = {};
        for (int c = 0; c < 64; c++) {
            float qr[8], kr[8];
            #pragma unroll
            for (int ii = 0; ii < 8; ii++) qr[ii] = sq[(tm*8 + ii)*SQ_STRIDE + c];
            *(float4*)&kr[0] = *(const float4*)&sk[c*SK_STRIDE + tn*8];
            *(float4*)&kr[4] = *(const float4*)&sk[c*SK_STRIDE + tn*8 + 4];
            #pragma unroll
            for (int ii = 0; ii < 8; ii++)
                #pragma unroll
                for (int jj = 0; jj < 8; jj++)
                    e[ii][jj] += qr[ii] * kr[jj];
        }
        #pragma unroll
        for (int ii = 0; ii < 8; ii++)
            #pragma unroll
            for (int jj = 0; jj < 8; jj++)
                sa[(tm*8 + ii)*SA_STRIDE + tn*8 + jj] = e[ii][jj];
    }
    __syncthreads();

    if (tid < 128) {
        float* rowp = &sa[tid*SA_STRIDE];
        float mx = -1e30f;
        #pragma unroll 4
        for (int m = 0; m < 128; m++) mx = fmaxf(mx, rowp[m]);
        float s = 0.f;
        #pragma unroll 4
        for (int m = 0; m < 128; m++) { float ev = __expf(rowp[m] - mx); rowp[m] = ev; s += ev; }
        float inv = 1.f / s;
        #pragma unroll 4
        for (int m = 0; m < 128; m++) rowp[m] *= inv;
    }

    const float gma = __ldg(gamma_p);
    const int lane = tid & 31;
    const int tw   = tid >> 5;

    for (int cc = 0; cc < Cc; cc += 64) {
        __syncthreads();
        for (int idx = tid * 4; idx < 64 * Ww; idx += 256 * 4) {
            int c  = idx >> 7;
            int m0 = idx & 127;
            float4 val = *(const float4*)(g_v + ((size_t)(b*Cc + cc + c)*Hh + h)*Ww + m0);
            *(float4*)&vs[c*SK_STRIDE + m0] = val;
        }
        __syncthreads();

        float o[4][8] = {};
        for (int m = 0; m < 128; m++) {
            float a0 = sa[(lane      )*SA_STRIDE + m];
            float a1 = sa[(lane + 32 )*SA_STRIDE + m];
            float a2 = sa[(lane + 64 )*SA_STRIDE + m];
            float a3 = sa[(lane + 96 )*SA_STRIDE + m];
            #pragma unroll
            for (int j = 0; j < 8; j++) {
                float vv = vs[(tw*8 + j)*SK_STRIDE + m];
                o[0][j] += a0 * vv;
                o[1][j] += a1 * vv;
                o[2][j] += a2 * vv;
                o[3][j] += a3 * vv;
            }
        }

        #pragma unroll
        for (int ii = 0; ii < 4; ii++) {
            int i = lane + 32*ii;
            #pragma unroll
            for (int j = 0; j < 8; j++) {
                int c = cc + tw*8 + j;
                size_t idx = ((size_t)(b*Cc + c)*Hh + h)*Ww + i;
                outp[idx] = gma * o[ii][j] + x[idx];
            }
        }
    }
}

// ---------------------------------------------------------------------------
extern "C" void kernel_launch(void* const* d_in, const int* in_sizes, int n_in,
                              void* d_out, int out_size)
{
    (void)in_sizes; (void)n_in; (void)out_size;
    const float* x     = (const float*)d_in[0];
    const float* Wq    = (const float*)d_in[1];
    const float* bq    = (const float*)d_in[2];
    const float* Wk    = (const float*)d_in[3];
    const float* bk    = (const float*)d_in[4];
    const float* Wv    = (const float*)d_in[5];
    const float* bv    = (const float*)d_in[6];
    const float* gamma = (const float*)d_in[7];
    float* out = (float*)d_out;

    prep_w<<<640, 128>>>(Wq, bq, Wk, bk, Wv, bv);

    dim3 gx(HW/64, Cc/64, Bn);
    prep_xt<<<gx, 256>>>(x);

    cudaFuncSetAttribute(qkv_gemm, cudaFuncAttributeMaxDynamicSharedMemorySize, SM_GEMM);
    dim3 gg(640/128, HW/128, Bn);   // m fastest for B-tile L2 reuse
    qkv_gemm<<<gg, 256, SM_GEMM>>>();

    cudaFuncSetAttribute(attn_kernel, cudaFuncAttributeMaxDynamicSharedMemorySize, SMEM_BYTES);
    attn_kernel<<<Bn*Hh, 256, SMEM_BYTES>>>(x, gamma, out);
}

// round 4
// speedup vs baseline: 2.1359x; 1.2665x over previous
#include <cuda_runtime.h>
#include <cuda_bf16.h>
#include <cstdint>

#define Bn 8
#define Cc 512
#define CQ 64
#define Hh 128
#define Ww 128
#define HW (Hh*Ww)   // 16384

// ---------------------------------------------------------------------------
// Device scratch
// ---------------------------------------------------------------------------
// packed (hi,lo) bf16 pairs, one uint32 per logical fp32 element
__device__ unsigned int g_qrow32[(size_t)Bn*Hh*128*64];   // [bh][i][c]
__device__ unsigned int g_krow32[(size_t)Bn*Hh*128*64];   // [bh][m][c]
__device__ unsigned int g_v32[(size_t)Bn*Cc*HW];          // [b][c][h][m]
__device__ __nv_bfloat16 g_xt_hi[(size_t)Bn*HW*Cc];       // xT[b][s][ch]
__device__ __nv_bfloat16 g_xt_lo[(size_t)Bn*HW*Cc];
__device__ __nv_bfloat16 g_w_hi[640*Cc];
__device__ __nv_bfloat16 g_w_lo[640*Cc];
__device__ float g_bias[640];

// ---------------------------------------------------------------------------
// helpers
// ---------------------------------------------------------------------------
__device__ __forceinline__ uint32_t smem_u32(const void* p) {
    uint32_t a;
    asm("{ .reg .u64 t; cvta.to.shared.u64 t, %1; cvt.u32.u64 %0, t; }" : "=r"(a) : "l"(p));
    return a;
}
__device__ __forceinline__ void cp16(uint32_t dst, const void* src) {
    asm volatile("cp.async.cg.shared.global [%0], [%1], 16;" :: "r"(dst), "l"(src));
}
#define CP_COMMIT()      asm volatile("cp.async.commit_group;" ::: "memory")
#define CP_WAIT_GROUP(n) asm volatile("cp.async.wait_group %0;" :: "n"(n) : "memory")

__device__ __forceinline__ void mma16816(float c[4], uint32_t a0, uint32_t a1, uint32_t a2, uint32_t a3,
                                         uint32_t b0, uint32_t b1) {
    asm volatile("mma.sync.aligned.m16n8k16.row.col.f32.bf16.bf16.f32 "
                 "{%0,%1,%2,%3}, {%4,%5,%6,%7}, {%8,%9}, {%0,%1,%2,%3};"
                 : "+f"(c[0]), "+f"(c[1]), "+f"(c[2]), "+f"(c[3])
                 : "r"(a0), "r"(a1), "r"(a2), "r"(a3), "r"(b0), "r"(b1));
}
__device__ __forceinline__ uint32_t prmt(uint32_t a, uint32_t b, uint32_t s) {
    uint32_t d;
    asm("prmt.b32 %0, %1, %2, %3;" : "=r"(d) : "r"(a), "r"(b), "r"(s));
    return d;
}
// pack fp32 -> (bf16 hi | bf16 lo << 16)
__device__ __forceinline__ uint32_t pack_hilo(float v) {
    __nv_bfloat16 h = __float2bfloat16(v);
    float r = v - __bfloat162float(h);
    __nv_bfloat16 l = __float2bfloat16(r);
    return (uint32_t)__bfloat16_as_ushort(h) | ((uint32_t)__bfloat16_as_ushort(l) << 16);
}

// ---------------------------------------------------------------------------
// Prep: W -> bf16 hi/lo (concat rows), bias concat
// ---------------------------------------------------------------------------
__global__ void prep_w(const float* __restrict__ Wq, const float* __restrict__ bq,
                       const float* __restrict__ Wk, const float* __restrict__ bk,
                       const float* __restrict__ Wv, const float* __restrict__ bv)
{
    int r = blockIdx.x;   // 0..639
    const float* src; float bias;
    if (r < 64)       { src = Wq + (size_t)r*Cc;        bias = bq[r]; }
    else if (r < 128) { src = Wk + (size_t)(r-64)*Cc;   bias = bk[r-64]; }
    else              { src = Wv + (size_t)(r-128)*Cc;  bias = bv[r-128]; }
    if (threadIdx.x == 0) g_bias[r] = bias;
    for (int c = threadIdx.x; c < Cc; c += blockDim.x) {
        float v = src[c];
        __nv_bfloat16 h = __float2bfloat16(v);
        float lo = v - __bfloat162float(h);
        g_w_hi[(size_t)r*Cc + c] = h;
        g_w_lo[(size_t)r*Cc + c] = __float2bfloat16(lo);
    }
}

// ---------------------------------------------------------------------------
// Prep: x[b][ch][s] -> xT hi/lo [b][s][ch]
// ---------------------------------------------------------------------------
__global__ void __launch_bounds__(256) prep_xt(const float* __restrict__ x)
{
    __shared__ float st[64*65];
    const int b = blockIdx.z, ch0 = blockIdx.y * 64, s0 = blockIdx.x * 64;
    const float* xb = x + ((size_t)b*Cc + ch0)*HW + s0;
    for (int i = threadIdx.x; i < 64*64; i += 256) {
        int ch = i >> 6, s = i & 63;
        st[ch*65 + s] = xb[(size_t)ch*HW + s];
    }
    __syncthreads();
    for (int u = threadIdx.x; u < 512; u += 256) {
        int s = u >> 3, c8 = (u & 7) * 8;
        uint32_t hi[4], lo[4];
        #pragma unroll
        for (int j = 0; j < 4; j++) {
            float a = st[(c8 + 2*j    )*65 + s];
            float c = st[(c8 + 2*j + 1)*65 + s];
            __nv_bfloat16 ah = __float2bfloat16(a), ch_ = __float2bfloat16(c);
            __nv_bfloat16 al = __float2bfloat16(a - __bfloat162float(ah));
            __nv_bfloat16 cl = __float2bfloat16(c - __bfloat162float(ch_));
            hi[j] = (uint32_t)__bfloat16_as_ushort(ah) | ((uint32_t)__bfloat16_as_ushort(ch_) << 16);
            lo[j] = (uint32_t)__bfloat16_as_ushort(al) | ((uint32_t)__bfloat16_as_ushort(cl) << 16);
        }
        size_t off = ((size_t)(b*HW + s0 + s))*Cc + ch0 + c8;
        *(uint4*)(g_xt_hi + off) = make_uint4(hi[0], hi[1], hi[2], hi[3]);
        *(uint4*)(g_xt_lo + off) = make_uint4(lo[0], lo[1], lo[2], lo[3]);
    }
}

// ---------------------------------------------------------------------------
// QKV GEMM via mma.sync bf16 (3-term hi/lo split); epilogue emits packed
// (hi,lo) bf16 into the attention-friendly layouts.
// ---------------------------------------------------------------------------
#define ROWB 80
#define SEG  10240
#define STAGE (4*SEG)
#define NSTAGE 3
#define SM_GEMM (NSTAGE*STAGE)

__device__ __forceinline__ void load_chunk(uint32_t sb, int tid, int k0, int m0, size_t bofs)
{
    const __nv_bfloat16* srcs[4] = {
        g_w_hi + (size_t)m0*Cc + k0,
        g_w_lo + (size_t)m0*Cc + k0,
        g_xt_hi + bofs + k0,
        g_xt_lo + bofs + k0 };
    #pragma unroll
    for (int i = tid; i < 2048; i += 256) {
        int seg = i >> 9;
        int r = (i & 511) >> 2, u = i & 3;
        cp16(sb + seg*SEG + r*ROWB + u*16, srcs[seg] + (size_t)r*Cc + u*8);
    }
    CP_COMMIT();
}

__global__ void __launch_bounds__(256, 1) qkv_gemm()
{
    extern __shared__ char smem[];
    const uint32_t sbase = smem_u32(smem);
    const int tid = threadIdx.x, wid = tid >> 5, lane = tid & 31;
    const int g = lane >> 2, q = lane & 3;
    const int m0 = blockIdx.x * 128;
    const int n0 = blockIdx.y * 128;
    const int b  = blockIdx.z;
    const int h  = n0 >> 7;             // n-tile of 128 == one h row
    const size_t bofs = ((size_t)b*HW + n0)*Cc;

    const int wm = wid & 1;
    const int wn = wid >> 1;

    float acc[4][4][4];
    #pragma unroll
    for (int i = 0; i < 4; i++)
        #pragma unroll
        for (int j = 0; j < 4; j++)
            #pragma unroll
            for (int e = 0; e < 4; e++) acc[i][j][e] = 0.f;

    load_chunk(sbase, tid, 0, m0, bofs);
    load_chunk(sbase + STAGE, tid, 32, m0, bofs);

    for (int c = 0; c < 16; c++) {
        CP_WAIT_GROUP(1);
        __syncthreads();
        if (c + 2 < 16)
            load_chunk(sbase + ((c+2) % NSTAGE)*STAGE, tid, (c+2)*32, m0, bofs);

        const uint32_t sb = sbase + (c % NSTAGE)*STAGE;
        #pragma unroll
        for (int ks = 0; ks < 2; ks++) {
            uint32_t ah[4][4], al[4][4], bh[4][2], bl[4][2];
            #pragma unroll
            for (int tm = 0; tm < 4; tm++) {
                uint32_t ra = sb + (wm*64 + tm*16 + g)*ROWB + ks*32 + q*4;
                ah[tm][0] = *(const uint32_t*)(smem + (ra - sbase));
                ah[tm][1] = *(const uint32_t*)(smem + (ra + 8*ROWB - sbase));
                ah[tm][2] = *(const uint32_t*)(smem + (ra + 16 - sbase));
                ah[tm][3] = *(const uint32_t*)(smem + (ra + 8*ROWB + 16 - sbase));
                al[tm][0] = *(const uint32_t*)(smem + (ra + SEG - sbase));
                al[tm][1] = *(const uint32_t*)(smem + (ra + SEG + 8*ROWB - sbase));
                al[tm][2] = *(const uint32_t*)(smem + (ra + SEG + 16 - sbase));
                al[tm][3] = *(const uint32_t*)(smem + (ra + SEG + 8*ROWB + 16 - sbase));
            }
            #pragma unroll
            for (int tn = 0; tn < 4; tn++) {
                uint32_t rb = sb + 2*SEG + (wn*32 + tn*8 + g)*ROWB + ks*32 + q*4;
                bh[tn][0] = *(const uint32_t*)(smem + (rb - sbase));
                bh[tn][1] = *(const uint32_t*)(smem + (rb + 16 - sbase));
                bl[tn][0] = *(const uint32_t*)(smem + (rb + SEG - sbase));
                bl[tn][1] = *(const uint32_t*)(smem + (rb + SEG + 16 - sbase));
            }
            #pragma unroll
            for (int tm = 0; tm < 4; tm++)
                #pragma unroll
                for (int tn = 0; tn < 4; tn++) {
                    mma16816(acc[tm][tn], ah[tm][0], ah[tm][1], ah[tm][2], ah[tm][3], bh[tn][0], bh[tn][1]);
                    mma16816(acc[tm][tn], ah[tm][0], ah[tm][1], ah[tm][2], ah[tm][3], bl[tn][0], bl[tn][1]);
                    mma16816(acc[tm][tn], al[tm][0], al[tm][1], al[tm][2], al[tm][3], bh[tn][0], bh[tn][1]);
                }
        }
        __syncthreads();
    }

    // Epilogue: bias, pack (hi,lo), route to attention layouts
    const int bh128 = b*128 + h;
    #pragma unroll
    for (int tm = 0; tm < 4; tm++) {
        int mrow = m0 + wm*64 + tm*16 + g;
        float bias0 = g_bias[mrow];
        float bias1 = g_bias[mrow + 8];
        #pragma unroll
        for (int tn = 0; tn < 4; tn++) {
            int w = wn*32 + tn*8 + q*2;  // w even
            uint32_t p0 = pack_hilo(acc[tm][tn][0] + bias0);
            uint32_t p1 = pack_hilo(acc[tm][tn][1] + bias0);
            uint32_t p2 = pack_hilo(acc[tm][tn][2] + bias1);
            uint32_t p3 = pack_hilo(acc[tm][tn][3] + bias1);
            #pragma unroll
            for (int rr = 0; rr < 2; rr++) {
                int oc = mrow + rr*8;
                uint32_t pa = rr ? p2 : p0;
                uint32_t pb = rr ? p3 : p1;
                if (oc < 64) {
                    int i = oc*2 + (w >> 6), cc = w & 63;
                    uint2 vv = make_uint2(pa, pb);
                    *(uint2*)&g_qrow32[((size_t)bh128*128 + i)*64 + cc] = vv;
                } else if (oc < 128) {
                    int cq = oc - 64, cc = w >> 1;
                    g_krow32[((size_t)bh128*128 + cq)*64 + cc]      = pa;
                    g_krow32[((size_t)bh128*128 + 64 + cq)*64 + cc] = pb;
                } else {
                    uint2 vv = make_uint2(pa, pb);
                    *(uint2*)&g_v32[(((size_t)b*Cc + oc - 128)*Hh + h)*Ww + w] = vv;
                }
            }
        }
    }
}

// ---------------------------------------------------------------------------
// Tensor-core attention kernel. One CTA per (b,h), 256 threads.
// ---------------------------------------------------------------------------
#define AQK_ROWB 272          // 64 uint32 + 16B pad
#define AA_ROWB  528          // 128 uint32 + 16B pad
#define AE_STRIDE 132         // floats
#define AST_STRIDE 132        // floats
#define AV_ROWB  528
#define AOFF_K   34816
#define AOFF_A   0
#define AOFF_E   69632
#define AOFF_ST  69632
#define AOFF_V   137216
#define AV_BUFB  33792        // 64 * 528
#define ATT_SMEM 204800

__device__ __forceinline__ void att_load_v(uint32_t sbv, int tid, int b, int h, int cc)
{
    const unsigned int* src0 = g_v32 + (((size_t)b*Cc + cc)*Hh + h)*Ww;
    #pragma unroll
    for (int i = tid; i < 2048; i += 256) {
        int r = i >> 5, u = i & 31;
        cp16(sbv + r*AV_ROWB + u*16, src0 + (size_t)r*HW + u*4);
    }
}

__global__ void __launch_bounds__(256, 1) attn_kernel(
    const float* __restrict__ x,
    const float* __restrict__ gamma_p,
    float* __restrict__ outp)
{
    extern __shared__ char smem[];
    const uint32_t sbase = smem_u32(smem);
    const int tid = threadIdx.x, wid = tid >> 5, lane = tid & 31;
    const int g = lane >> 2, q = lane & 3;
    const int bh = blockIdx.x;
    const int b = bh >> 7, h = bh & 127;
    const float gma = gamma_p[0];

    // prefetch v chunk 0 | q,k | v chunk 1
    att_load_v(sbase + AOFF_V, tid, b, h, 0);
    CP_COMMIT();
    {
        const unsigned int* srcs[2] = { g_qrow32 + (size_t)bh*128*64, g_krow32 + (size_t)bh*128*64 };
        #pragma unroll
        for (int i = tid; i < 4096; i += 256) {
            int arr = i >> 11, r = (i & 2047) >> 4, u = i & 15;
            cp16(sbase + arr*AOFF_K + r*AQK_ROWB + u*16, srcs[arr] + (size_t)r*64 + u*4);
        }
        CP_COMMIT();
    }
    att_load_v(sbase + AOFF_V + AV_BUFB, tid, b, h, 64);
    CP_COMMIT();

    CP_WAIT_GROUP(1);          // v0 + qk ready
    __syncthreads();

    const int wi = wid & 3;    // i 32-tiles
    const int wj = wid >> 2;   // m/c 64-(energy) / 32-(out) group

    // ---- energy: E[i][m] = sum_c qrow[i][c]*krowT[m][c], 3-term ----
    {
        float e[2][8][4];
        #pragma unroll
        for (int a1 = 0; a1 < 2; a1++)
            #pragma unroll
            for (int a2 = 0; a2 < 8; a2++)
                #pragma unroll
                for (int a3 = 0; a3 < 4; a3++) e[a1][a2][a3] = 0.f;

        #pragma unroll
        for (int ks = 0; ks < 4; ks++) {
            uint32_t ah[2][4], al[2][4], bh_[8][2], bl_[8][2];
            #pragma unroll
            for (int ti = 0; ti < 2; ti++) {
                uint32_t ra = (wi*32 + ti*16 + g)*AQK_ROWB + ks*64 + q*8;
                uint2 w00 = *(const uint2*)(smem + ra);
                uint2 w10 = *(const uint2*)(smem + ra + 8*AQK_ROWB);
                uint2 w01 = *(const uint2*)(smem + ra + 32);
                uint2 w11 = *(const uint2*)(smem + ra + 8*AQK_ROWB + 32);
                ah[ti][0] = prmt(w00.x, w00.y, 0x5410); al[ti][0] = prmt(w00.x, w00.y, 0x7632);
                ah[ti][1] = prmt(w10.x, w10.y, 0x5410); al[ti][1] = prmt(w10.x, w10.y, 0x7632);
                ah[ti][2] = prmt(w01.x, w01.y, 0x5410); al[ti][2] = prmt(w01.x, w01.y, 0x7632);
                ah[ti][3] = prmt(w11.x, w11.y, 0x5410); al[ti][3] = prmt(w11.x, w11.y, 0x7632);
            }
            #pragma unroll
            for (int tn = 0; tn < 8; tn++) {
                uint32_t rb = AOFF_K + (wj*64 + tn*8 + g)*AQK_ROWB + ks*64 + q*8;
                uint2 u0 = *(const uint2*)(smem + rb);
                uint2 u1 = *(const uint2*)(smem + rb + 32);
                bh_[tn][0] = prmt(u0.x, u0.y, 0x5410); bl_[tn][0] = prmt(u0.x, u0.y, 0x7632);
                bh_[tn][1] = prmt(u1.x, u1.y, 0x5410); bl_[tn][1] = prmt(u1.x, u1.y, 0x7632);
            }
            #pragma unroll
            for (int ti = 0; ti < 2; ti++)
                #pragma unroll
                for (int tn = 0; tn < 8; tn++) {
                    mma16816(e[ti][tn], ah[ti][0], ah[ti][1], ah[ti][2], ah[ti][3], bh_[tn][0], bh_[tn][1]);
                    mma16816(e[ti][tn], al[ti][0], al[ti][1], al[ti][2], al[ti][3], bh_[tn][0], bh_[tn][1]);
                    mma16816(e[ti][tn], ah[ti][0], ah[ti][1], ah[ti][2], ah[ti][3], bl_[tn][0], bl_[tn][1]);
                }
        }
        float* Ef = (float*)(smem + AOFF_E);
        #pragma unroll
        for (int ti = 0; ti < 2; ti++)
            #pragma unroll
            for (int tn = 0; tn < 8; tn++) {
                int ri = wi*32 + ti*16 + g, cj = wj*64 + tn*8 + 2*q;
                *(float2*)&Ef[ri*AE_STRIDE + cj]     = make_float2(e[ti][tn][0], e[ti][tn][1]);
                *(float2*)&Ef[(ri+8)*AE_STRIDE + cj] = make_float2(e[ti][tn][2], e[ti][tn][3]);
            }
    }
    __syncthreads();

    // ---- softmax + pack A (hi,lo) ----
    {
        float* Ef = (float*)(smem + AOFF_E);
        int i = tid >> 1, half = tid & 1;
        float* row = Ef + i*AE_STRIDE + half*64;
        float mx = -1e30f;
        #pragma unroll 8
        for (int j = 0; j < 64; j++) mx = fmaxf(mx, row[j]);
        mx = fmaxf(mx, __shfl_xor_sync(0xFFFFFFFFu, mx, 1));
        float s = 0.f;
        #pragma unroll 8
        for (int j = 0; j < 64; j++) { float p = __expf(row[j] - mx); row[j] = p; s += p; }
        s += __shfl_xor_sync(0xFFFFFFFFu, s, 1);
        float inv = 1.f / s;
        uint32_t* arow = (uint32_t*)(smem + AOFF_A + i*AA_ROWB) + half*64;
        #pragma unroll 8
        for (int j = 0; j < 64; j++) arow[j] = pack_hilo(row[j] * inv);
    }
    __syncthreads();

    // ---- out chunks: out[i][c] = sum_m A[i][m]*v[c][m], 8 chunks of 64 c ----
    float* STf = (float*)(smem + AOFF_ST);
    for (int ci = 0; ci < 8; ci++) {
        if (ci < 7) { CP_WAIT_GROUP(1); } else { CP_WAIT_GROUP(0); }
        __syncthreads();

        const uint32_t vb = AOFF_V + (ci & 1)*AV_BUFB;
        float o[2][4][4];
        #pragma unroll
        for (int a1 = 0; a1 < 2; a1++)
            #pragma unroll
            for (int a2 = 0; a2 < 4; a2++)
                #pragma unroll
                for (int a3 = 0; a3 < 4; a3++) o[a1][a2][a3] = 0.f;

        #pragma unroll
        for (int ks = 0; ks < 8; ks++) {
            uint32_t ah[2][4], al[2][4], bh_[4][2], bl_[4][2];
            #pragma unroll
            for (int ti = 0; ti < 2; ti++) {
                uint32_t ra = AOFF_A + (wi*32 + ti*16 + g)*AA_ROWB + ks*64 + q*8;
                uint2 w00 = *(const uint2*)(smem + ra);
                uint2 w10 = *(const uint2*)(smem + ra + 8*AA_ROWB);
                uint2 w01 = *(const uint2*)(smem + ra + 32);
                uint2 w11 = *(const uint2*)(smem + ra + 8*AA_ROWB + 32);
                ah[ti][0] = prmt(w00.x, w00.y, 0x5410); al[ti][0] = prmt(w00.x, w00.y, 0x7632);
                ah[ti][1] = prmt(w10.x, w10.y, 0x5410); al[ti][1] = prmt(w10.x, w10.y, 0x7632);
                ah[ti][2] = prmt(w01.x, w01.y, 0x5410); al[ti][2] = prmt(w01.x, w01.y, 0x7632);
                ah[ti][3] = prmt(w11.x, w11.y, 0x5410); al[ti][3] = prmt(w11.x, w11.y, 0x7632);
            }
            #pragma unroll
            for (int tn = 0; tn < 4; tn++) {
                uint32_t rb = vb + (wj*32 + tn*8 + g)*AV_ROWB + ks*64 + q*8;
                uint2 u0 = *(const uint2*)(smem + rb);
                uint2 u1 = *(const uint2*)(smem + rb + 32);
                bh_[tn][0] = prmt(u0.x, u0.y, 0x5410); bl_[tn][0] = prmt(u0.x, u0.y, 0x7632);
                bh_[tn][1] = prmt(u1.x, u1.y, 0x5410); bl_[tn][1] = prmt(u1.x, u1.y, 0x7632);
            }
            #pragma unroll
            for (int ti = 0; ti < 2; ti++)
                #pragma unroll
                for (int tn = 0; tn < 4; tn++) {
                    mma16816(o[ti][tn], ah[ti][0], ah[ti][1], ah[ti][2], ah[ti][3], bh_[tn][0], bh_[tn][1]);
                    mma16816(o[ti][tn], al[ti][0], al[ti][1], al[ti][2], al[ti][3], bh_[tn][0], bh_[tn][1]);
                    mma16816(o[ti][tn], ah[ti][0], ah[ti][1], ah[ti][2], ah[ti][3], bl_[tn][0], bl_[tn][1]);
                }
        }
        __syncthreads();   // all warps done reading vbuf[ci&1]

        if (ci + 2 < 8) { att_load_v(sbase + vb, tid, b, h, (ci+2)*64); CP_COMMIT(); }

        // stage out[i][c'] -> ST[c'][i]
        #pragma unroll
        for (int ti = 0; ti < 2; ti++)
            #pragma unroll
            for (int tn = 0; tn < 4; tn++) {
                int ri = wi*32 + ti*16 + g, cj = wj*32 + tn*8 + 2*q;
                STf[cj*AST_STRIDE + ri]          = o[ti][tn][0];
                STf[(cj+1)*AST_STRIDE + ri]      = o[ti][tn][1];
                STf[cj*AST_STRIDE + ri + 8]      = o[ti][tn][2];
                STf[(cj+1)*AST_STRIDE + ri + 8]  = o[ti][tn][3];
            }
        __syncthreads();

        // coalesced writeback: out[b][c][h][i] = gma*o + x
        #pragma unroll
        for (int rr = 0; rr < 8; rr++) {
            int r = wid*8 + rr;
            int c = ci*64 + r;
            size_t gofs = (((size_t)b*Cc + c)*Hh + h)*Ww + lane*4;
            float4 xr = *(const float4*)(x + gofs);
            float4 ov = *(const float4*)(STf + r*AST_STRIDE + lane*4);
            float4 res = make_float4(gma*ov.x + xr.x, gma*ov.y + xr.y,
                                     gma*ov.z + xr.z, gma*ov.w + xr.w);
            *(float4*)(outp + gofs) = res;
        }
    }
}

// ---------------------------------------------------------------------------
extern "C" void kernel_launch(void* const* d_in, const int* in_sizes, int n_in,
                              void* d_out, int out_size)
{
    (void)in_sizes; (void)n_in; (void)out_size;
    const float* x     = (const float*)d_in[0];
    const float* Wq    = (const float*)d_in[1];
    const float* bq    = (const float*)d_in[2];
    const float* Wk    = (const float*)d_in[3];
    const float* bk    = (const float*)d_in[4];
    const float* Wv    = (const float*)d_in[5];
    const float* bv    = (const float*)d_in[6];
    const float* gamma = (const float*)d_in[7];
    float* out = (float*)d_out;

    prep_w<<<640, 128>>>(Wq, bq, Wk, bk, Wv, bv);

    dim3 gx(HW/64, Cc/64, Bn);
    prep_xt<<<gx, 256>>>(x);

    cudaFuncSetAttribute(qkv_gemm, cudaFuncAttributeMaxDynamicSharedMemorySize, SM_GEMM);
    dim3 gg(640/128, HW/128, Bn);
    qkv_gemm<<<gg, 256, SM_GEMM>>>();

    cudaFuncSetAttribute(attn_kernel, cudaFuncAttributeMaxDynamicSharedMemorySize, ATT_SMEM);
    attn_kernel<<<Bn*Hh, 256, ATT_SMEM>>>(x, gamma, out);
}

// round 5
// speedup vs baseline: 3.6767x; 1.7214x over previous
#include <cuda_runtime.h>
#include <cuda_fp16.h>
#include <cstdint>

#define Bn 8
#define Cc 512
#define CQ 64
#define Hh 128
#define Ww 128
#define HW (Hh*Ww)   // 16384

// ---------------------------------------------------------------------------
// Device scratch
// ---------------------------------------------------------------------------
__device__ unsigned int g_qrow32[(size_t)Bn*Hh*128*64];   // [bh][i][c] packed (hi,lo) fp16
__device__ unsigned int g_krow32[(size_t)Bn*Hh*128*64];   // [bh][m][c] packed (hi,lo) fp16
__device__ __half g_v16[(size_t)Bn*Cc*HW];                // [b][c][s] fp16 single
__device__ __half g_xt_hi[(size_t)Bn*HW*Cc];              // xT[b][s][ch]
__device__ __half g_xt_lo[(size_t)Bn*HW*Cc];
__device__ __half g_w_hi[640*Cc];
__device__ __half g_w_lo[640*Cc];
__device__ float g_bias[640];

// ---------------------------------------------------------------------------
// helpers
// ---------------------------------------------------------------------------
__device__ __forceinline__ uint32_t smem_u32(const void* p) {
    uint32_t a;
    asm("{ .reg .u64 t; cvta.to.shared.u64 t, %1; cvt.u32.u64 %0, t; }" : "=r"(a) : "l"(p));
    return a;
}
__device__ __forceinline__ void cp16(uint32_t dst, const void* src) {
    asm volatile("cp.async.cg.shared.global [%0], [%1], 16;" :: "r"(dst), "l"(src));
}
#define CP_COMMIT()      asm volatile("cp.async.commit_group;" ::: "memory")
#define CP_WAIT_GROUP(n) asm volatile("cp.async.wait_group %0;" :: "n"(n) : "memory")

__device__ __forceinline__ void mma_f16(float c[4], uint32_t a0, uint32_t a1, uint32_t a2, uint32_t a3,
                                        uint32_t b0, uint32_t b1) {
    asm volatile("mma.sync.aligned.m16n8k16.row.col.f32.f16.f16.f32 "
                 "{%0,%1,%2,%3}, {%4,%5,%6,%7}, {%8,%9}, {%0,%1,%2,%3};"
                 : "+f"(c[0]), "+f"(c[1]), "+f"(c[2]), "+f"(c[3])
                 : "r"(a0), "r"(a1), "r"(a2), "r"(a3), "r"(b0), "r"(b1));
}
__device__ __forceinline__ uint32_t prmt(uint32_t a, uint32_t b, uint32_t s) {
    uint32_t d;
    asm("prmt.b32 %0, %1, %2, %3;" : "=r"(d) : "r"(a), "r"(b), "r"(s));
    return d;
}
// pack fp32 -> (fp16 hi | fp16 lo << 16)
__device__ __forceinline__ uint32_t pack_hilo(float v) {
    __half h = __float2half_rn(v);
    float r = v - __half2float(h);
    __half l = __float2half_rn(r);
    return (uint32_t)__half_as_ushort(h) | ((uint32_t)__half_as_ushort(l) << 16);
}
__device__ __forceinline__ uint32_t pack2h(float a, float b) {
    __half ha = __float2half_rn(a), hb = __float2half_rn(b);
    return (uint32_t)__half_as_ushort(ha) | ((uint32_t)__half_as_ushort(hb) << 16);
}

// ---------------------------------------------------------------------------
// Prep: W -> fp16 hi/lo (concat rows), bias concat
// ---------------------------------------------------------------------------
__global__ void prep_w(const float* __restrict__ Wq, const float* __restrict__ bq,
                       const float* __restrict__ Wk, const float* __restrict__ bk,
                       const float* __restrict__ Wv, const float* __restrict__ bv)
{
    int r = blockIdx.x;   // 0..639
    const float* src; float bias;
    if (r < 64)       { src = Wq + (size_t)r*Cc;        bias = bq[r]; }
    else if (r < 128) { src = Wk + (size_t)(r-64)*Cc;   bias = bk[r-64]; }
    else              { src = Wv + (size_t)(r-128)*Cc;  bias = bv[r-128]; }
    if (threadIdx.x == 0) g_bias[r] = bias;
    for (int c = threadIdx.x; c < Cc; c += blockDim.x) {
        float v = src[c];
        __half h = __float2half_rn(v);
        g_w_hi[(size_t)r*Cc + c] = h;
        g_w_lo[(size_t)r*Cc + c] = __float2half_rn(v - __half2float(h));
    }
}

// ---------------------------------------------------------------------------
// Prep: x[b][ch][s] -> xT hi/lo [b][s][ch]
// ---------------------------------------------------------------------------
__global__ void __launch_bounds__(256) prep_xt(const float* __restrict__ x)
{
    __shared__ float st[64*65];
    const int b = blockIdx.z, ch0 = blockIdx.y * 64, s0 = blockIdx.x * 64;
    const float* xb = x + ((size_t)b*Cc + ch0)*HW + s0;
    for (int i = threadIdx.x; i < 64*64; i += 256) {
        int ch = i >> 6, s = i & 63;
        st[ch*65 + s] = xb[(size_t)ch*HW + s];
    }
    __syncthreads();
    for (int u = threadIdx.x; u < 512; u += 256) {
        int s = u >> 3, c8 = (u & 7) * 8;
        uint32_t hi[4], lo[4];
        #pragma unroll
        for (int j = 0; j < 4; j++) {
            float a = st[(c8 + 2*j    )*65 + s];
            float c = st[(c8 + 2*j + 1)*65 + s];
            __half ah = __float2half_rn(a), ch_ = __float2half_rn(c);
            __half al = __float2half_rn(a - __half2float(ah));
            __half cl = __float2half_rn(c - __half2float(ch_));
            hi[j] = (uint32_t)__half_as_ushort(ah) | ((uint32_t)__half_as_ushort(ch_) << 16);
            lo[j] = (uint32_t)__half_as_ushort(al) | ((uint32_t)__half_as_ushort(cl) << 16);
        }
        size_t off = ((size_t)(b*HW + s0 + s))*Cc + ch0 + c8;
        *(uint4*)(g_xt_hi + off) = make_uint4(hi[0], hi[1], hi[2], hi[3]);
        *(uint4*)(g_xt_lo + off) = make_uint4(lo[0], lo[1], lo[2], lo[3]);
    }
}

// ---------------------------------------------------------------------------
// Shared GEMM constants
// ---------------------------------------------------------------------------
#define ROWB 80
#define SEG  10240            // 128 rows * 80B
#define NSTAGE 3

// ---------------------------------------------------------------------------
// QK GEMM: rows 0..127 of W, 3-term fp16 hi/lo. One n-tile(=h row) per CTA.
// smem stage: Ah|Al|Bh|Bl (4 segs). 122880B total.
// ---------------------------------------------------------------------------
#define STAGE_QK (4*SEG)
#define SM_QK (NSTAGE*STAGE_QK)

__device__ __forceinline__ void load_chunk_qk(uint32_t sb, int tid, int k0, size_t bofs)
{
    const __half* srcs[4] = {
        g_w_hi + k0, g_w_lo + k0,
        g_xt_hi + bofs + k0, g_xt_lo + bofs + k0 };
    #pragma unroll
    for (int i = tid; i < 2048; i += 256) {
        int seg = i >> 9;
        int r = (i & 511) >> 2, u = i & 3;
        cp16(sb + seg*SEG + r*ROWB + u*16, srcs[seg] + (size_t)r*Cc + u*8);
    }
    CP_COMMIT();
}

__global__ void __launch_bounds__(256, 1) qkv_gemm_qk()
{
    extern __shared__ char smem[];
    const uint32_t sbase = smem_u32(smem);
    const int tid = threadIdx.x, wid = tid >> 5, lane = tid & 31;
    const int g = lane >> 2, q = lane & 3;
    const int h = blockIdx.x;          // n-tile == h row
    const int b = blockIdx.y;
    const int n0 = h * 128;
    const size_t bofs = ((size_t)b*HW + n0)*Cc;
    const int wm = wid & 1, wn = wid >> 1;

    float acc[4][4][4];
    #pragma unroll
    for (int i = 0; i < 4; i++)
        #pragma unroll
        for (int j = 0; j < 4; j++)
            #pragma unroll
            for (int e = 0; e < 4; e++) acc[i][j][e] = 0.f;

    load_chunk_qk(sbase, tid, 0, bofs);
    load_chunk_qk(sbase + STAGE_QK, tid, 32, bofs);

    for (int c = 0; c < 16; c++) {
        CP_WAIT_GROUP(1);
        __syncthreads();
        if (c + 2 < 16)
            load_chunk_qk(sbase + ((c+2) % NSTAGE)*STAGE_QK, tid, (c+2)*32, bofs);

        const uint32_t sb = sbase + (c % NSTAGE)*STAGE_QK;
        #pragma unroll
        for (int ks = 0; ks < 2; ks++) {
            uint32_t ah[4][4], al[4][4], bh[4][2], bl[4][2];
            #pragma unroll
            for (int tm = 0; tm < 4; tm++) {
                uint32_t ra = sb + (wm*64 + tm*16 + g)*ROWB + ks*32 + q*4;
                ah[tm][0] = *(const uint32_t*)(smem + (ra - sbase));
                ah[tm][1] = *(const uint32_t*)(smem + (ra + 8*ROWB - sbase));
                ah[tm][2] = *(const uint32_t*)(smem + (ra + 16 - sbase));
                ah[tm][3] = *(const uint32_t*)(smem + (ra + 8*ROWB + 16 - sbase));
                al[tm][0] = *(const uint32_t*)(smem + (ra + SEG - sbase));
                al[tm][1] = *(const uint32_t*)(smem + (ra + SEG + 8*ROWB - sbase));
                al[tm][2] = *(const uint32_t*)(smem + (ra + SEG + 16 - sbase));
                al[tm][3] = *(const uint32_t*)(smem + (ra + SEG + 8*ROWB + 16 - sbase));
            }
            #pragma unroll
            for (int tn = 0; tn < 4; tn++) {
                uint32_t rb = sb + 2*SEG + (wn*32 + tn*8 + g)*ROWB + ks*32 + q*4;
                bh[tn][0] = *(const uint32_t*)(smem + (rb - sbase));
                bh[tn][1] = *(const uint32_t*)(smem + (rb + 16 - sbase));
                bl[tn][0] = *(const uint32_t*)(smem + (rb + SEG - sbase));
                bl[tn][1] = *(const uint32_t*)(smem + (rb + SEG + 16 - sbase));
            }
            #pragma unroll
            for (int tm = 0; tm < 4; tm++)
                #pragma unroll
                for (int tn = 0; tn < 4; tn++) {
                    mma_f16(acc[tm][tn], ah[tm][0], ah[tm][1], ah[tm][2], ah[tm][3], bh[tn][0], bh[tn][1]);
                    mma_f16(acc[tm][tn], ah[tm][0], ah[tm][1], ah[tm][2], ah[tm][3], bl[tn][0], bl[tn][1]);
                    mma_f16(acc[tm][tn], al[tm][0], al[tm][1], al[tm][2], al[tm][3], bh[tn][0], bh[tn][1]);
                }
        }
        __syncthreads();
    }

    // Epilogue: bias, pack (hi,lo), route to q/k attention layouts
    const int bh128 = b*128 + h;
    #pragma unroll
    for (int tm = 0; tm < 4; tm++) {
        int mrow = wm*64 + tm*16 + g;
        float bias0 = g_bias[mrow];
        float bias1 = g_bias[mrow + 8];
        #pragma unroll
        for (int tn = 0; tn < 4; tn++) {
            int w = wn*32 + tn*8 + q*2;  // even
            uint32_t p0 = pack_hilo(acc[tm][tn][0] + bias0);
            uint32_t p1 = pack_hilo(acc[tm][tn][1] + bias0);
            uint32_t p2 = pack_hilo(acc[tm][tn][2] + bias1);
            uint32_t p3 = pack_hilo(acc[tm][tn][3] + bias1);
            #pragma unroll
            for (int rr = 0; rr < 2; rr++) {
                int oc = mrow + rr*8;
                uint32_t pa = rr ? p2 : p0;
                uint32_t pb = rr ? p3 : p1;
                if (oc < 64) {
                    int i = oc*2 + (w >> 6), cc = w & 63;
                    *(uint2*)&g_qrow32[((size_t)bh128*128 + i)*64 + cc] = make_uint2(pa, pb);
                } else {
                    int cq = oc - 64, cc = w >> 1;
                    g_krow32[((size_t)bh128*128 + cq)*64 + cc]      = pa;
                    g_krow32[((size_t)bh128*128 + 64 + cq)*64 + cc] = pb;
                }
            }
        }
    }
}

// ---------------------------------------------------------------------------
// V GEMM: rows 128..639 of W, 1-term fp16 (hi only). smem stage: Ah|Bh.
// ---------------------------------------------------------------------------
#define STAGE_V (2*SEG)
#define SM_V (NSTAGE*STAGE_V)   // 61440

__device__ __forceinline__ void load_chunk_v(uint32_t sb, int tid, int k0, int m0, size_t bofs)
{
    const __half* srcs[2] = {
        g_w_hi + (size_t)(128 + m0)*Cc + k0,
        g_xt_hi + bofs + k0 };
    #pragma unroll
    for (int i = tid; i < 1024; i += 256) {
        int seg = i >> 9;
        int r = (i & 511) >> 2, u = i & 3;
        cp16(sb + seg*SEG + r*ROWB + u*16, srcs[seg] + (size_t)r*Cc + u*8);
    }
    CP_COMMIT();
}

__global__ void __launch_bounds__(256, 2) qkv_gemm_v()
{
    extern __shared__ char smem[];
    const uint32_t sbase = smem_u32(smem);
    const int tid = threadIdx.x, wid = tid >> 5, lane = tid & 31;
    const int g = lane >> 2, q = lane & 3;
    const int m0 = blockIdx.x * 128;    // within v rows (0..383)
    const int n0 = blockIdx.y * 128;
    const int b  = blockIdx.z;
    const size_t bofs = ((size_t)b*HW + n0)*Cc;
    const int wm = wid & 1, wn = wid >> 1;

    float acc[4][4][4];
    #pragma unroll
    for (int i = 0; i < 4; i++)
        #pragma unroll
        for (int j = 0; j < 4; j++)
            #pragma unroll
            for (int e = 0; e < 4; e++) acc[i][j][e] = 0.f;

    load_chunk_v(sbase, tid, 0, m0, bofs);
    load_chunk_v(sbase + STAGE_V, tid, 32, m0, bofs);

    for (int c = 0; c < 16; c++) {
        CP_WAIT_GROUP(1);
        __syncthreads();
        if (c + 2 < 16)
            load_chunk_v(sbase + ((c+2) % NSTAGE)*STAGE_V, tid, (c+2)*32, m0, bofs);

        const uint32_t sb = sbase + (c % NSTAGE)*STAGE_V;
        #pragma unroll
        for (int ks = 0; ks < 2; ks++) {
            uint32_t ah[4][4], bh[4][2];
            #pragma unroll
            for (int tm = 0; tm < 4; tm++) {
                uint32_t ra = sb + (wm*64 + tm*16 + g)*ROWB + ks*32 + q*4;
                ah[tm][0] = *(const uint32_t*)(smem + (ra - sbase));
                ah[tm][1] = *(const uint32_t*)(smem + (ra + 8*ROWB - sbase));
                ah[tm][2] = *(const uint32_t*)(smem + (ra + 16 - sbase));
                ah[tm][3] = *(const uint32_t*)(smem + (ra + 8*ROWB + 16 - sbase));
            }
            #pragma unroll
            for (int tn = 0; tn < 4; tn++) {
                uint32_t rb = sb + SEG + (wn*32 + tn*8 + g)*ROWB + ks*32 + q*4;
                bh[tn][0] = *(const uint32_t*)(smem + (rb - sbase));
                bh[tn][1] = *(const uint32_t*)(smem + (rb + 16 - sbase));
            }
            #pragma unroll
            for (int tm = 0; tm < 4; tm++)
                #pragma unroll
                for (int tn = 0; tn < 4; tn++)
                    mma_f16(acc[tm][tn], ah[tm][0], ah[tm][1], ah[tm][2], ah[tm][3], bh[tn][0], bh[tn][1]);
        }
        __syncthreads();
    }

    // Epilogue: fp16 single to g_v16[b][c][s]
    #pragma unroll
    for (int tm = 0; tm < 4; tm++) {
        int cv = m0 + wm*64 + tm*16 + g;
        float bias0 = g_bias[128 + cv];
        float bias1 = g_bias[128 + cv + 8];
        #pragma unroll
        for (int tn = 0; tn < 4; tn++) {
            int n = n0 + wn*32 + tn*8 + q*2;
            uint32_t pa = pack2h(acc[tm][tn][0] + bias0, acc[tm][tn][1] + bias0);
            uint32_t pb = pack2h(acc[tm][tn][2] + bias1, acc[tm][tn][3] + bias1);
            *(uint32_t*)&g_v16[((size_t)b*Cc + cv)*HW + n]     = pa;
            *(uint32_t*)&g_v16[((size_t)b*Cc + cv + 8)*HW + n] = pb;
        }
    }
}

// ---------------------------------------------------------------------------
// Tensor-core attention kernel. One CTA per (b,h), 256 threads.
// ---------------------------------------------------------------------------
#define AQK_ROWB 272          // 64 uint32 + 16B pad
#define AA_ROWB  272          // 128 fp16 + 16B pad
#define AV_ROWB  272          // 128 fp16 + 16B pad
#define AE_STRIDE 132         // floats
#define AST_STRIDE 132        // floats
#define AOFF_Q   0
#define AOFF_K   34816
#define AOFF_A   0            // overlays q after energy
#define AOFF_E   69632
#define AOFF_ST  69632        // overlays E after softmax
#define AOFF_V   137216
#define AV_BUFB  17408        // 64 * 272
#define ATT_SMEM 172032

__device__ __forceinline__ void att_load_v(uint32_t sbv, int tid, int b, int h, int cc)
{
    const __half* src0 = g_v16 + (((size_t)b*Cc + cc)*Hh + h)*Ww;
    #pragma unroll
    for (int i = tid; i < 1024; i += 256) {
        int r = i >> 4, u = i & 15;
        cp16(sbv + r*AV_ROWB + u*16, src0 + (size_t)r*HW + u*8);
    }
}

__global__ void __launch_bounds__(256, 1) attn_kernel(
    const float* __restrict__ x,
    const float* __restrict__ gamma_p,
    float* __restrict__ outp)
{
    extern __shared__ char smem[];
    const uint32_t sbase = smem_u32(smem);
    const int tid = threadIdx.x, wid = tid >> 5, lane = tid & 31;
    const int g = lane >> 2, q = lane & 3;
    const int bh = blockIdx.x;
    const int b = bh >> 7, h = bh & 127;
    const float gma = gamma_p[0];

    // prefetch v chunk 0 | q,k | v chunk 1
    att_load_v(sbase + AOFF_V, tid, b, h, 0);
    CP_COMMIT();
    {
        const unsigned int* srcs[2] = { g_qrow32 + (size_t)bh*128*64, g_krow32 + (size_t)bh*128*64 };
        #pragma unroll
        for (int i = tid; i < 4096; i += 256) {
            int arr = i >> 11, r = (i & 2047) >> 4, u = i & 15;
            cp16(sbase + arr*AOFF_K + r*AQK_ROWB + u*16, srcs[arr] + (size_t)r*64 + u*4);
        }
        CP_COMMIT();
    }
    att_load_v(sbase + AOFF_V + AV_BUFB, tid, b, h, 64);
    CP_COMMIT();

    CP_WAIT_GROUP(1);          // v0 + qk ready
    __syncthreads();

    const int wi = wid & 3;
    const int wj = wid >> 2;

    // ---- energy: E[i][m] = sum_c qrow[i][c]*krowT[m][c], 3-term fp16 ----
    {
        float e[2][8][4];
        #pragma unroll
        for (int a1 = 0; a1 < 2; a1++)
            #pragma unroll
            for (int a2 = 0; a2 < 8; a2++)
                #pragma unroll
                for (int a3 = 0; a3 < 4; a3++) e[a1][a2][a3] = 0.f;

        #pragma unroll
        for (int ks = 0; ks < 4; ks++) {
            uint32_t ah[2][4], al[2][4], bh_[8][2], bl_[8][2];
            #pragma unroll
            for (int ti = 0; ti < 2; ti++) {
                uint32_t ra = AOFF_Q + (wi*32 + ti*16 + g)*AQK_ROWB + ks*64 + q*8;
                uint2 w00 = *(const uint2*)(smem + ra);
                uint2 w10 = *(const uint2*)(smem + ra + 8*AQK_ROWB);
                uint2 w01 = *(const uint2*)(smem + ra + 32);
                uint2 w11 = *(const uint2*)(smem + ra + 8*AQK_ROWB + 32);
                ah[ti][0] = prmt(w00.x, w00.y, 0x5410); al[ti][0] = prmt(w00.x, w00.y, 0x7632);
                ah[ti][1] = prmt(w10.x, w10.y, 0x5410); al[ti][1] = prmt(w10.x, w10.y, 0x7632);
                ah[ti][2] = prmt(w01.x, w01.y, 0x5410); al[ti][2] = prmt(w01.x, w01.y, 0x7632);
                ah[ti][3] = prmt(w11.x, w11.y, 0x5410); al[ti][3] = prmt(w11.x, w11.y, 0x7632);
            }
            #pragma unroll
            for (int tn = 0; tn < 8; tn++) {
                uint32_t rb = AOFF_K + (wj*64 + tn*8 + g)*AQK_ROWB + ks*64 + q*8;
                uint2 u0 = *(const uint2*)(smem + rb);
                uint2 u1 = *(const uint2*)(smem + rb + 32);
                bh_[tn][0] = prmt(u0.x, u0.y, 0x5410); bl_[tn][0] = prmt(u0.x, u0.y, 0x7632);
                bh_[tn][1] = prmt(u1.x, u1.y, 0x5410); bl_[tn][1] = prmt(u1.x, u1.y, 0x7632);
            }
            #pragma unroll
            for (int ti = 0; ti < 2; ti++)
                #pragma unroll
                for (int tn = 0; tn < 8; tn++) {
                    mma_f16(e[ti][tn], ah[ti][0], ah[ti][1], ah[ti][2], ah[ti][3], bh_[tn][0], bh_[tn][1]);
                    mma_f16(e[ti][tn], al[ti][0], al[ti][1], al[ti][2], al[ti][3], bh_[tn][0], bh_[tn][1]);
                    mma_f16(e[ti][tn], ah[ti][0], ah[ti][1], ah[ti][2], ah[ti][3], bl_[tn][0], bl_[tn][1]);
                }
        }
        float* Ef = (float*)(smem + AOFF_E);
        #pragma unroll
        for (int ti = 0; ti < 2; ti++)
            #pragma unroll
            for (int tn = 0; tn < 8; tn++) {
                int ri = wi*32 + ti*16 + g, cj = wj*64 + tn*8 + 2*q;
                *(float2*)&Ef[ri*AE_STRIDE + cj]     = make_float2(e[ti][tn][0], e[ti][tn][1]);
                *(float2*)&Ef[(ri+8)*AE_STRIDE + cj] = make_float2(e[ti][tn][2], e[ti][tn][3]);
            }
    }
    __syncthreads();

    // ---- softmax + pack A fp16 single (overlays q region) ----
    {
        float* Ef = (float*)(smem + AOFF_E);
        int i = tid >> 1, half_sel = tid & 1;
        float* row = Ef + i*AE_STRIDE + half_sel*64;
        float mx = -1e30f;
        #pragma unroll 8
        for (int j = 0; j < 64; j++) mx = fmaxf(mx, row[j]);
        mx = fmaxf(mx, __shfl_xor_sync(0xFFFFFFFFu, mx, 1));
        float s = 0.f;
        #pragma unroll 8
        for (int j = 0; j < 64; j++) { float p = __expf(row[j] - mx); row[j] = p; s += p; }
        s += __shfl_xor_sync(0xFFFFFFFFu, s, 1);
        float inv = 1.f / s;
        uint32_t* arow = (uint32_t*)(smem + AOFF_A + i*AA_ROWB + half_sel*128);
        #pragma unroll 8
        for (int j = 0; j < 64; j += 2)
            arow[j >> 1] = pack2h(row[j]*inv, row[j+1]*inv);
    }
    __syncthreads();

    // ---- out chunks: out[i][c] = sum_m A[i][m]*v[c][m], 8 chunks of 64 c ----
    float* STf = (float*)(smem + AOFF_ST);
    for (int ci = 0; ci < 8; ci++) {
        if (ci < 7) { CP_WAIT_GROUP(1); } else { CP_WAIT_GROUP(0); }
        __syncthreads();

        const uint32_t vb = AOFF_V + (ci & 1)*AV_BUFB;
        float o[2][4][4];
        #pragma unroll
        for (int a1 = 0; a1 < 2; a1++)
            #pragma unroll
            for (int a2 = 0; a2 < 4; a2++)
                #pragma unroll
                for (int a3 = 0; a3 < 4; a3++) o[a1][a2][a3] = 0.f;

        #pragma unroll
        for (int ks = 0; ks < 8; ks++) {
            uint32_t a0[2], a1r[2], a2[2], a3[2], b0[4], b1[4];
            #pragma unroll
            for (int ti = 0; ti < 2; ti++) {
                uint32_t ra = AOFF_A + (wi*32 + ti*16 + g)*AA_ROWB + ks*32 + q*4;
                a0[ti]  = *(const uint32_t*)(smem + ra);
                a1r[ti] = *(const uint32_t*)(smem + ra + 8*AA_ROWB);
                a2[ti]  = *(const uint32_t*)(smem + ra + 16);
                a3[ti]  = *(const uint32_t*)(smem + ra + 8*AA_ROWB + 16);
            }
            #pragma unroll
            for (int tn = 0; tn < 4; tn++) {
                uint32_t rb = vb + (wj*32 + tn*8 + g)*AV_ROWB + ks*32 + q*4;
                b0[tn] = *(const uint32_t*)(smem + rb);
                b1[tn] = *(const uint32_t*)(smem + rb + 16);
            }
            #pragma unroll
            for (int ti = 0; ti < 2; ti++)
                #pragma unroll
                for (int tn = 0; tn < 4; tn++)
                    mma_f16(o[ti][tn], a0[ti], a1r[ti], a2[ti], a3[ti], b0[tn], b1[tn]);
        }
        __syncthreads();   // all warps done reading vbuf[ci&1]

        if (ci + 2 < 8) { att_load_v(sbase + vb, tid, b, h, (ci+2)*64); CP_COMMIT(); }

        // stage out[i][c'] -> ST[c'][i]
        #pragma unroll
        for (int ti = 0; ti < 2; ti++)
            #pragma unroll
            for (int tn = 0; tn < 4; tn++) {
                int ri = wi*32 + ti*16 + g, cj = wj*32 + tn*8 + 2*q;
                STf[cj*AST_STRIDE + ri]          = o[ti][tn][0];
                STf[(cj+1)*AST_STRIDE + ri]      = o[ti][tn][1];
                STf[cj*AST_STRIDE + ri + 8]      = o[ti][tn][2];
                STf[(cj+1)*AST_STRIDE + ri + 8]  = o[ti][tn][3];
            }
        __syncthreads();

        // coalesced writeback: out[b][c][h][i] = gma*o + x
        #pragma unroll
        for (int rr = 0; rr < 8; rr++) {
            int r = wid*8 + rr;
            int c = ci*64 + r;
            size_t gofs = (((size_t)b*Cc + c)*Hh + h)*Ww + lane*4;
            float4 xr = *(const float4*)(x + gofs);
            float4 ov = *(const float4*)(STf + r*AST_STRIDE + lane*4);
            *(float4*)(outp + gofs) = make_float4(gma*ov.x + xr.x, gma*ov.y + xr.y,
                                                  gma*ov.z + xr.z, gma*ov.w + xr.w);
        }
    }
}

// ---------------------------------------------------------------------------
extern "C" void kernel_launch(void* const* d_in, const int* in_sizes, int n_in,
                              void* d_out, int out_size)
{
    (void)in_sizes; (void)n_in; (void)out_size;
    const float* x     = (const float*)d_in[0];
    const float* Wq    = (const float*)d_in[1];
    const float* bq    = (const float*)d_in[2];
    const float* Wk    = (const float*)d_in[3];
    const float* bk    = (const float*)d_in[4];
    const float* Wv    = (const float*)d_in[5];
    const float* bv    = (const float*)d_in[6];
    const float* gamma = (const float*)d_in[7];
    float* out = (float*)d_out;

    prep_w<<<640, 128>>>(Wq, bq, Wk, bk, Wv, bv);

    dim3 gx(HW/64, Cc/64, Bn);
    prep_xt<<<gx, 256>>>(x);

    cudaFuncSetAttribute(qkv_gemm_qk, cudaFuncAttributeMaxDynamicSharedMemorySize, SM_QK);
    qkv_gemm_qk<<<dim3(128, Bn), 256, SM_QK>>>();

    cudaFuncSetAttribute(qkv_gemm_v, cudaFuncAttributeMaxDynamicSharedMemorySize, SM_V);
    qkv_gemm_v<<<dim3(4, 128, Bn), 256, SM_V>>>();

    cudaFuncSetAttribute(attn_kernel, cudaFuncAttributeMaxDynamicSharedMemorySize, ATT_SMEM);
    attn_kernel<<<Bn*Hh, 256, ATT_SMEM>>>(x, gamma, out);
}

// round 6
// speedup vs baseline: 3.8960x; 1.0596x over previous
#include <cuda_runtime.h>
#include <cuda_fp16.h>
#include <cstdint>

#define Bn 8
#define Cc 512
#define CQ 64
#define Hh 128
#define Ww 128
#define HW (Hh*Ww)   // 16384

// ---------------------------------------------------------------------------
// Device scratch
// ---------------------------------------------------------------------------
__device__ unsigned int g_qrow32[(size_t)Bn*Hh*128*64];   // [bh][i][c] packed (hi,lo) fp16
__device__ unsigned int g_krow32[(size_t)Bn*Hh*128*64];   // [bh][m][c] packed (hi,lo) fp16
__device__ __half g_v16[(size_t)Bn*Cc*HW];                // [b][c][s] fp16 single
__device__ __half g_xt_hi[(size_t)Bn*HW*Cc];              // xT[b][s][ch]
__device__ __half g_xt_lo[(size_t)Bn*HW*Cc];
__device__ __half g_w_hi[640*Cc];
__device__ __half g_w_lo[640*Cc];
__device__ float g_bias[640];

// ---------------------------------------------------------------------------
// helpers
// ---------------------------------------------------------------------------
__device__ __forceinline__ uint32_t smem_u32(const void* p) {
    uint32_t a;
    asm("{ .reg .u64 t; cvta.to.shared.u64 t, %1; cvt.u32.u64 %0, t; }" : "=r"(a) : "l"(p));
    return a;
}
__device__ __forceinline__ void cp16(uint32_t dst, const void* src) {
    asm volatile("cp.async.cg.shared.global [%0], [%1], 16;" :: "r"(dst), "l"(src));
}
#define CP_COMMIT()      asm volatile("cp.async.commit_group;" ::: "memory")
#define CP_WAIT_GROUP(n) asm volatile("cp.async.wait_group %0;" :: "n"(n) : "memory")

__device__ __forceinline__ void mma_f16(float c[4], uint32_t a0, uint32_t a1, uint32_t a2, uint32_t a3,
                                        uint32_t b0, uint32_t b1) {
    asm volatile("mma.sync.aligned.m16n8k16.row.col.f32.f16.f16.f32 "
                 "{%0,%1,%2,%3}, {%4,%5,%6,%7}, {%8,%9}, {%0,%1,%2,%3};"
                 : "+f"(c[0]), "+f"(c[1]), "+f"(c[2]), "+f"(c[3])
                 : "r"(a0), "r"(a1), "r"(a2), "r"(a3), "r"(b0), "r"(b1));
}
__device__ __forceinline__ void ldsm4(uint32_t& r0, uint32_t& r1, uint32_t& r2, uint32_t& r3,
                                      uint32_t addr) {
    asm volatile("ldmatrix.sync.aligned.m8n8.x4.shared.b16 {%0,%1,%2,%3}, [%4];"
                 : "=r"(r0), "=r"(r1), "=r"(r2), "=r"(r3) : "r"(addr));
}
__device__ __forceinline__ uint32_t prmt(uint32_t a, uint32_t b, uint32_t s) {
    uint32_t d;
    asm("prmt.b32 %0, %1, %2, %3;" : "=r"(d) : "r"(a), "r"(b), "r"(s));
    return d;
}
__device__ __forceinline__ uint32_t pack_hilo(float v) {
    __half h = __float2half_rn(v);
    float r = v - __half2float(h);
    __half l = __float2half_rn(r);
    return (uint32_t)__half_as_ushort(h) | ((uint32_t)__half_as_ushort(l) << 16);
}
__device__ __forceinline__ uint32_t pack2h(float a, float b) {
    __half ha = __float2half_rn(a), hb = __float2half_rn(b);
    return (uint32_t)__half_as_ushort(ha) | ((uint32_t)__half_as_ushort(hb) << 16);
}

// ---------------------------------------------------------------------------
// Prep: W -> fp16 hi/lo (concat rows), bias concat
// ---------------------------------------------------------------------------
__global__ void prep_w(const float* __restrict__ Wq, const float* __restrict__ bq,
                       const float* __restrict__ Wk, const float* __restrict__ bk,
                       const float* __restrict__ Wv, const float* __restrict__ bv)
{
    int r = blockIdx.x;
    const float* src; float bias;
    if (r < 64)       { src = Wq + (size_t)r*Cc;        bias = bq[r]; }
    else if (r < 128) { src = Wk + (size_t)(r-64)*Cc;   bias = bk[r-64]; }
    else              { src = Wv + (size_t)(r-128)*Cc;  bias = bv[r-128]; }
    if (threadIdx.x == 0) g_bias[r] = bias;
    for (int c = threadIdx.x; c < Cc; c += blockDim.x) {
        float v = src[c];
        __half h = __float2half_rn(v);
        g_w_hi[(size_t)r*Cc + c] = h;
        g_w_lo[(size_t)r*Cc + c] = __float2half_rn(v - __half2float(h));
    }
}

// ---------------------------------------------------------------------------
// Prep: x[b][ch][s] -> xT hi/lo [b][s][ch]
// ---------------------------------------------------------------------------
__global__ void __launch_bounds__(256) prep_xt(const float* __restrict__ x)
{
    __shared__ float st[64*65];
    const int b = blockIdx.z, ch0 = blockIdx.y * 64, s0 = blockIdx.x * 64;
    const float* xb = x + ((size_t)b*Cc + ch0)*HW + s0;
    for (int i = threadIdx.x; i < 64*64; i += 256) {
        int ch = i >> 6, s = i & 63;
        st[ch*65 + s] = xb[(size_t)ch*HW + s];
    }
    __syncthreads();
    for (int u = threadIdx.x; u < 512; u += 256) {
        int s = u >> 3, c8 = (u & 7) * 8;
        uint32_t hi[4], lo[4];
        #pragma unroll
        for (int j = 0; j < 4; j++) {
            float a = st[(c8 + 2*j    )*65 + s];
            float c = st[(c8 + 2*j + 1)*65 + s];
            __half ah = __float2half_rn(a), ch_ = __float2half_rn(c);
            __half al = __float2half_rn(a - __half2float(ah));
            __half cl = __float2half_rn(c - __half2float(ch_));
            hi[j] = (uint32_t)__half_as_ushort(ah) | ((uint32_t)__half_as_ushort(ch_) << 16);
            lo[j] = (uint32_t)__half_as_ushort(al) | ((uint32_t)__half_as_ushort(cl) << 16);
        }
        size_t off = ((size_t)(b*HW + s0 + s))*Cc + ch0 + c8;
        *(uint4*)(g_xt_hi + off) = make_uint4(hi[0], hi[1], hi[2], hi[3]);
        *(uint4*)(g_xt_lo + off) = make_uint4(lo[0], lo[1], lo[2], lo[3]);
    }
}

// ---------------------------------------------------------------------------
// Shared GEMM constants
// ---------------------------------------------------------------------------
#define ROWB 80
#define SEG  10240            // 128 rows * 80B
#define NSTAGE 3

// ---------------------------------------------------------------------------
// QK GEMM: rows 0..127 of W, 3-term fp16 hi/lo. 512 threads, warp tile 32x32.
// smem stage: Ah|Al|Bh|Bl. ldmatrix fragment loads.
// ---------------------------------------------------------------------------
#define STAGE_QK (4*SEG)
#define SM_QK (NSTAGE*STAGE_QK)

__device__ __forceinline__ void load_chunk_qk(uint32_t sb, int tid, int k0, size_t bofs)
{
    const __half* srcs[4] = {
        g_w_hi + k0, g_w_lo + k0,
        g_xt_hi + bofs + k0, g_xt_lo + bofs + k0 };
    #pragma unroll
    for (int i = tid; i < 2048; i += 512) {
        int seg = i >> 9;
        int r = (i & 511) >> 2, u = i & 3;
        cp16(sb + seg*SEG + r*ROWB + u*16, srcs[seg] + (size_t)r*Cc + u*8);
    }
    CP_COMMIT();
}

__global__ void __launch_bounds__(512, 1) qkv_gemm_qk()
{
    extern __shared__ char smem[];
    const uint32_t sbase = smem_u32(smem);
    const int tid = threadIdx.x, wid = tid >> 5, lane = tid & 31;
    const int g = lane >> 2, q = lane & 3;
    const int h = blockIdx.x;
    const int b = blockIdx.y;
    const int n0 = h * 128;
    const size_t bofs = ((size_t)b*HW + n0)*Cc;
    const int wm = wid & 3, wn = wid >> 2;
    const int lmat = lane >> 3, lrow = lane & 7;   // ldmatrix addressing

    float acc[2][4][4];
    #pragma unroll
    for (int i = 0; i < 2; i++)
        #pragma unroll
        for (int j = 0; j < 4; j++)
            #pragma unroll
            for (int e = 0; e < 4; e++) acc[i][j][e] = 0.f;

    load_chunk_qk(sbase, tid, 0, bofs);
    load_chunk_qk(sbase + STAGE_QK, tid, 32, bofs);

    for (int c = 0; c < 16; c++) {
        CP_WAIT_GROUP(1);
        __syncthreads();
        if (c + 2 < 16)
            load_chunk_qk(sbase + ((c+2) % NSTAGE)*STAGE_QK, tid, (c+2)*32, bofs);

        const uint32_t sb = sbase + (c % NSTAGE)*STAGE_QK;
        #pragma unroll
        for (int ks = 0; ks < 2; ks++) {
            uint32_t ah[2][4], al[2][4], bh[4][2], bl[4][2];
            #pragma unroll
            for (int tm = 0; tm < 2; tm++) {
                uint32_t ra = sb + (wm*32 + tm*16 + (lmat&1)*8 + lrow)*ROWB + ks*32 + (lmat>>1)*16;
                ldsm4(ah[tm][0], ah[tm][1], ah[tm][2], ah[tm][3], ra);
                ldsm4(al[tm][0], al[tm][1], al[tm][2], al[tm][3], ra + SEG);
            }
            #pragma unroll
            for (int tp = 0; tp < 2; tp++) {
                uint32_t rb = sb + 2*SEG + (wn*32 + (tp*2 + (lmat>>1))*8 + lrow)*ROWB + ks*32 + (lmat&1)*16;
                ldsm4(bh[tp*2][0], bh[tp*2][1], bh[tp*2+1][0], bh[tp*2+1][1], rb);
                ldsm4(bl[tp*2][0], bl[tp*2][1], bl[tp*2+1][0], bl[tp*2+1][1], rb + SEG);
            }
            #pragma unroll
            for (int tm = 0; tm < 2; tm++)
                #pragma unroll
                for (int tn = 0; tn < 4; tn++) {
                    mma_f16(acc[tm][tn], ah[tm][0], ah[tm][1], ah[tm][2], ah[tm][3], bh[tn][0], bh[tn][1]);
                    mma_f16(acc[tm][tn], ah[tm][0], ah[tm][1], ah[tm][2], ah[tm][3], bl[tn][0], bl[tn][1]);
                    mma_f16(acc[tm][tn], al[tm][0], al[tm][1], al[tm][2], al[tm][3], bh[tn][0], bh[tn][1]);
                }
        }
        __syncthreads();
    }

    // Epilogue: bias, pack (hi,lo), route to q/k attention layouts
    const int bh128 = b*128 + h;
    #pragma unroll
    for (int tm = 0; tm < 2; tm++) {
        int mrow = wm*32 + tm*16 + g;
        float bias0 = g_bias[mrow];
        float bias1 = g_bias[mrow + 8];
        #pragma unroll
        for (int tn = 0; tn < 4; tn++) {
            int w = wn*32 + tn*8 + q*2;  // even
            uint32_t p0 = pack_hilo(acc[tm][tn][0] + bias0);
            uint32_t p1 = pack_hilo(acc[tm][tn][1] + bias0);
            uint32_t p2 = pack_hilo(acc[tm][tn][2] + bias1);
            uint32_t p3 = pack_hilo(acc[tm][tn][3] + bias1);
            #pragma unroll
            for (int rr = 0; rr < 2; rr++) {
                int oc = mrow + rr*8;
                uint32_t pa = rr ? p2 : p0;
                uint32_t pb = rr ? p3 : p1;
                if (oc < 64) {
                    int i = oc*2 + (w >> 6), cc = w & 63;
                    *(uint2*)&g_qrow32[((size_t)bh128*128 + i)*64 + cc] = make_uint2(pa, pb);
                } else {
                    int cq = oc - 64, cc = w >> 1;
                    g_krow32[((size_t)bh128*128 + cq)*64 + cc]      = pa;
                    g_krow32[((size_t)bh128*128 + 64 + cq)*64 + cc] = pb;
                }
            }
        }
    }
}

// ---------------------------------------------------------------------------
// V GEMM: rows 128..639 of W, 1-term fp16 (hi only). 256 threads, 2 CTAs/SM,
// ldmatrix fragment loads.
// ---------------------------------------------------------------------------
#define STAGE_V (2*SEG)
#define SM_V (NSTAGE*STAGE_V)   // 61440

__device__ __forceinline__ void load_chunk_v(uint32_t sb, int tid, int k0, int m0, size_t bofs)
{
    const __half* srcs[2] = {
        g_w_hi + (size_t)(128 + m0)*Cc + k0,
        g_xt_hi + bofs + k0 };
    #pragma unroll
    for (int i = tid; i < 1024; i += 256) {
        int seg = i >> 9;
        int r = (i & 511) >> 2, u = i & 3;
        cp16(sb + seg*SEG + r*ROWB + u*16, srcs[seg] + (size_t)r*Cc + u*8);
    }
    CP_COMMIT();
}

__global__ void __launch_bounds__(256, 2) qkv_gemm_v()
{
    extern __shared__ char smem[];
    const uint32_t sbase = smem_u32(smem);
    const int tid = threadIdx.x, wid = tid >> 5, lane = tid & 31;
    const int g = lane >> 2, q = lane & 3;
    const int m0 = blockIdx.x * 128;    // within v rows (0..383)
    const int n0 = blockIdx.y * 128;
    const int b  = blockIdx.z;
    const size_t bofs = ((size_t)b*HW + n0)*Cc;
    const int wm = wid & 1, wn = wid >> 1;
    const int lmat = lane >> 3, lrow = lane & 7;

    float acc[4][4][4];
    #pragma unroll
    for (int i = 0; i < 4; i++)
        #pragma unroll
        for (int j = 0; j < 4; j++)
            #pragma unroll
            for (int e = 0; e < 4; e++) acc[i][j][e] = 0.f;

    load_chunk_v(sbase, tid, 0, m0, bofs);
    load_chunk_v(sbase + STAGE_V, tid, 32, m0, bofs);

    for (int c = 0; c < 16; c++) {
        CP_WAIT_GROUP(1);
        __syncthreads();
        if (c + 2 < 16)
            load_chunk_v(sbase + ((c+2) % NSTAGE)*STAGE_V, tid, (c+2)*32, m0, bofs);

        const uint32_t sb = sbase + (c % NSTAGE)*STAGE_V;
        #pragma unroll
        for (int ks = 0; ks < 2; ks++) {
            uint32_t ah[4][4], bh[4][2];
            #pragma unroll
            for (int tm = 0; tm < 4; tm++) {
                uint32_t ra = sb + (wm*64 + tm*16 + (lmat&1)*8 + lrow)*ROWB + ks*32 + (lmat>>1)*16;
                ldsm4(ah[tm][0], ah[tm][1], ah[tm][2], ah[tm][3], ra);
            }
            #pragma unroll
            for (int tp = 0; tp < 2; tp++) {
                uint32_t rb = sb + SEG + (wn*32 + (tp*2 + (lmat>>1))*8 + lrow)*ROWB + ks*32 + (lmat&1)*16;
                ldsm4(bh[tp*2][0], bh[tp*2][1], bh[tp*2+1][0], bh[tp*2+1][1], rb);
            }
            #pragma unroll
            for (int tm = 0; tm < 4; tm++)
                #pragma unroll
                for (int tn = 0; tn < 4; tn++)
                    mma_f16(acc[tm][tn], ah[tm][0], ah[tm][1], ah[tm][2], ah[tm][3], bh[tn][0], bh[tn][1]);
        }
        __syncthreads();
    }

    // Epilogue: fp16 single to g_v16[b][c][s]
    #pragma unroll
    for (int tm = 0; tm < 4; tm++) {
        int cv = m0 + wm*64 + tm*16 + g;
        float bias0 = g_bias[128 + cv];
        float bias1 = g_bias[128 + cv + 8];
        #pragma unroll
        for (int tn = 0; tn < 4; tn++) {
            int n = n0 + wn*32 + tn*8 + q*2;
            uint32_t pa = pack2h(acc[tm][tn][0] + bias0, acc[tm][tn][1] + bias0);
            uint32_t pb = pack2h(acc[tm][tn][2] + bias1, acc[tm][tn][3] + bias1);
            *(uint32_t*)&g_v16[((size_t)b*Cc + cv)*HW + n]     = pa;
            *(uint32_t*)&g_v16[((size_t)b*Cc + cv + 8)*HW + n] = pb;
        }
    }
}

// ---------------------------------------------------------------------------
// Tensor-core attention kernel. One CTA per (b,h), 512 threads.
// ---------------------------------------------------------------------------
#define AQK_ROWB 272          // 64 uint32 + 16B pad
#define AA_ROWB  272          // 128 fp16 + 16B pad
#define AV_ROWB  272          // 128 fp16 + 16B pad
#define AE_STRIDE 132         // floats
#define AST_STRIDE 132        // floats
#define AOFF_Q   0
#define AOFF_K   34816
#define AOFF_A   0            // overlays q after energy
#define AOFF_E   69632
#define AOFF_ST  69632        // overlays E after softmax
#define AOFF_V   137216
#define AV_BUFB  17408        // 64 * 272
#define ATT_SMEM 172032

__device__ __forceinline__ void att_load_v(uint32_t sbv, int tid, int b, int h, int cc)
{
    const __half* src0 = g_v16 + (((size_t)b*Cc + cc)*Hh + h)*Ww;
    #pragma unroll
    for (int i = tid; i < 1024; i += 512) {
        int r = i >> 4, u = i & 15;
        cp16(sbv + r*AV_ROWB + u*16, src0 + (size_t)r*HW + u*8);
    }
}

__global__ void __launch_bounds__(512, 1) attn_kernel(
    const float* __restrict__ x,
    const float* __restrict__ gamma_p,
    float* __restrict__ outp)
{
    extern __shared__ char smem[];
    const uint32_t sbase = smem_u32(smem);
    const int tid = threadIdx.x, wid = tid >> 5, lane = tid & 31;
    const int g = lane >> 2, q = lane & 3;
    const int bh = blockIdx.x;
    const int b = bh >> 7, h = bh & 127;
    const float gma = gamma_p[0];

    // prefetch v chunk 0 | q,k | v chunk 1
    att_load_v(sbase + AOFF_V, tid, b, h, 0);
    CP_COMMIT();
    {
        const unsigned int* srcs[2] = { g_qrow32 + (size_t)bh*128*64, g_krow32 + (size_t)bh*128*64 };
        #pragma unroll
        for (int i = tid; i < 4096; i += 512) {
            int arr = i >> 11, r = (i & 2047) >> 4, u = i & 15;
            cp16(sbase + arr*AOFF_K + r*AQK_ROWB + u*16, srcs[arr] + (size_t)r*64 + u*4);
        }
        CP_COMMIT();
    }
    att_load_v(sbase + AOFF_V + AV_BUFB, tid, b, h, 64);
    CP_COMMIT();

    CP_WAIT_GROUP(1);          // v0 + qk ready
    __syncthreads();

    const int wi = wid & 3;    // i 32-tile
    const int wj = wid >> 2;   // m 32-cols (energy) / c 16-cols (out)

    // ---- energy: E[i][m] = sum_c qrow[i][c]*krowT[m][c], 3-term fp16 ----
    {
        float e[2][4][4];
        #pragma unroll
        for (int a1 = 0; a1 < 2; a1++)
            #pragma unroll
            for (int a2 = 0; a2 < 4; a2++)
                #pragma unroll
                for (int a3 = 0; a3 < 4; a3++) e[a1][a2][a3] = 0.f;

        #pragma unroll
        for (int ks = 0; ks < 4; ks++) {
            uint32_t ah[2][4], al[2][4], bh_[4][2], bl_[4][2];
            #pragma unroll
            for (int ti = 0; ti < 2; ti++) {
                uint32_t ra = AOFF_Q + (wi*32 + ti*16 + g)*AQK_ROWB + ks*64 + q*8;
                uint2 w00 = *(const uint2*)(smem + ra);
                uint2 w10 = *(const uint2*)(smem + ra + 8*AQK_ROWB);
                uint2 w01 = *(const uint2*)(smem + ra + 32);
                uint2 w11 = *(const uint2*)(smem + ra + 8*AQK_ROWB + 32);
                ah[ti][0] = prmt(w00.x, w00.y, 0x5410); al[ti][0] = prmt(w00.x, w00.y, 0x7632);
                ah[ti][1] = prmt(w10.x, w10.y, 0x5410); al[ti][1] = prmt(w10.x, w10.y, 0x7632);
                ah[ti][2] = prmt(w01.x, w01.y, 0x5410); al[ti][2] = prmt(w01.x, w01.y, 0x7632);
                ah[ti][3] = prmt(w11.x, w11.y, 0x5410); al[ti][3] = prmt(w11.x, w11.y, 0x7632);
            }
            #pragma unroll
            for (int tn = 0; tn < 4; tn++) {
                uint32_t rb = AOFF_K + (wj*32 + tn*8 + g)*AQK_ROWB + ks*64 + q*8;
                uint2 u0 = *(const uint2*)(smem + rb);
                uint2 u1 = *(const uint2*)(smem + rb + 32);
                bh_[tn][0] = prmt(u0.x, u0.y, 0x5410); bl_[tn][0] = prmt(u0.x, u0.y, 0x7632);
                bh_[tn][1] = prmt(u1.x, u1.y, 0x5410); bl_[tn][1] = prmt(u1.x, u1.y, 0x7632);
            }
            #pragma unroll
            for (int ti = 0; ti < 2; ti++)
                #pragma unroll
                for (int tn = 0; tn < 4; tn++) {
                    mma_f16(e[ti][tn], ah[ti][0], ah[ti][1], ah[ti][2], ah[ti][3], bh_[tn][0], bh_[tn][1]);
                    mma_f16(e[ti][tn], al[ti][0], al[ti][1], al[ti][2], al[ti][3], bh_[tn][0], bh_[tn][1]);
                    mma_f16(e[ti][tn], ah[ti][0], ah[ti][1], ah[ti][2], ah[ti][3], bl_[tn][0], bl_[tn][1]);
                }
        }
        float* Ef = (float*)(smem + AOFF_E);
        #pragma unroll
        for (int ti = 0; ti < 2; ti++)
            #pragma unroll
            for (int tn = 0; tn < 4; tn++) {
                int ri = wi*32 + ti*16 + g, cj = wj*32 + tn*8 + 2*q;
                *(float2*)&Ef[ri*AE_STRIDE + cj]     = make_float2(e[ti][tn][0], e[ti][tn][1]);
                *(float2*)&Ef[(ri+8)*AE_STRIDE + cj] = make_float2(e[ti][tn][2], e[ti][tn][3]);
            }
    }
    __syncthreads();

    // ---- softmax + pack A fp16 single (overlays q region), 4 threads/row ----
    {
        float* Ef = (float*)(smem + AOFF_E);
        int i = tid >> 2, qt = tid & 3;
        float* row = Ef + i*AE_STRIDE + qt*32;
        float mx = -1e30f;
        #pragma unroll 8
        for (int j = 0; j < 32; j++) mx = fmaxf(mx, row[j]);
        mx = fmaxf(mx, __shfl_xor_sync(0xFFFFFFFFu, mx, 1));
        mx = fmaxf(mx, __shfl_xor_sync(0xFFFFFFFFu, mx, 2));
        float s = 0.f;
        #pragma unroll 8
        for (int j = 0; j < 32; j++) { float p = __expf(row[j] - mx); row[j] = p; s += p; }
        s += __shfl_xor_sync(0xFFFFFFFFu, s, 1);
        s += __shfl_xor_sync(0xFFFFFFFFu, s, 2);
        float inv = 1.f / s;
        uint32_t* arow = (uint32_t*)(smem + AOFF_A + i*AA_ROWB + qt*64);
        #pragma unroll 8
        for (int j = 0; j < 32; j += 2)
            arow[j >> 1] = pack2h(row[j]*inv, row[j+1]*inv);
    }
    __syncthreads();

    // ---- out chunks: out[i][c] = sum_m A[i][m]*v[c][m], 8 chunks of 64 c ----
    float* STf = (float*)(smem + AOFF_ST);
    for (int ci = 0; ci < 8; ci++) {
        if (ci < 7) { CP_WAIT_GROUP(1); } else { CP_WAIT_GROUP(0); }
        __syncthreads();

        const uint32_t vb = AOFF_V + (ci & 1)*AV_BUFB;
        float o[2][2][4];
        #pragma unroll
        for (int a1 = 0; a1 < 2; a1++)
            #pragma unroll
            for (int a2 = 0; a2 < 2; a2++)
                #pragma unroll
                for (int a3 = 0; a3 < 4; a3++) o[a1][a2][a3] = 0.f;

        #pragma unroll
        for (int ks = 0; ks < 8; ks++) {
            uint32_t a0[2], a1r[2], a2[2], a3[2], b0[2], b1[2];
            #pragma unroll
            for (int ti = 0; ti < 2; ti++) {
                uint32_t ra = AOFF_A + (wi*32 + ti*16 + g)*AA_ROWB + ks*32 + q*4;
                a0[ti]  = *(const uint32_t*)(smem + ra);
                a1r[ti] = *(const uint32_t*)(smem + ra + 8*AA_ROWB);
                a2[ti]  = *(const uint32_t*)(smem + ra + 16);
                a3[ti]  = *(const uint32_t*)(smem + ra + 8*AA_ROWB + 16);
            }
            #pragma unroll
            for (int tn = 0; tn < 2; tn++) {
                uint32_t rb = vb + (wj*16 + tn*8 + g)*AV_ROWB + ks*32 + q*4;
                b0[tn] = *(const uint32_t*)(smem + rb);
                b1[tn] = *(const uint32_t*)(smem + rb + 16);
            }
            #pragma unroll
            for (int ti = 0; ti < 2; ti++)
                #pragma unroll
                for (int tn = 0; tn < 2; tn++)
                    mma_f16(o[ti][tn], a0[ti], a1r[ti], a2[ti], a3[ti], b0[tn], b1[tn]);
        }
        __syncthreads();   // all warps done reading vbuf[ci&1]

        if (ci + 2 < 8) { att_load_v(sbase + vb, tid, b, h, (ci+2)*64); CP_COMMIT(); }

        // stage out[i][c'] -> ST[c'][i]
        #pragma unroll
        for (int ti = 0; ti < 2; ti++)
            #pragma unroll
            for (int tn = 0; tn < 2; tn++) {
                int ri = wi*32 + ti*16 + g, cj = wj*16 + tn*8 + 2*q;
                STf[cj*AST_STRIDE + ri]          = o[ti][tn][0];
                STf[(cj+1)*AST_STRIDE + ri]      = o[ti][tn][1];
                STf[cj*AST_STRIDE + ri + 8]      = o[ti][tn][2];
                STf[(cj+1)*AST_STRIDE + ri + 8]  = o[ti][tn][3];
            }
        __syncthreads();

        // coalesced writeback: out[b][c][h][i] = gma*o + x
        #pragma unroll
        for (int rr = 0; rr < 4; rr++) {
            int r = wid*4 + rr;
            int c = ci*64 + r;
            size_t gofs = (((size_t)b*Cc + c)*Hh + h)*Ww + lane*4;
            float4 xr = *(const float4*)(x + gofs);
            float4 ov = *(const float4*)(STf + r*AST_STRIDE + lane*4);
            *(float4*)(outp + gofs) = make_float4(gma*ov.x + xr.x, gma*ov.y + xr.y,
                                                  gma*ov.z + xr.z, gma*ov.w + xr.w);
        }
    }
}

// ---------------------------------------------------------------------------
extern "C" void kernel_launch(void* const* d_in, const int* in_sizes, int n_in,
                              void* d_out, int out_size)
{
    (void)in_sizes; (void)n_in; (void)out_size;
    const float* x     = (const float*)d_in[0];
    const float* Wq    = (const float*)d_in[1];
    const float* bq    = (const float*)d_in[2];
    const float* Wk    = (const float*)d_in[3];
    const float* bk    = (const float*)d_in[4];
    const float* Wv    = (const float*)d_in[5];
    const float* bv    = (const float*)d_in[6];
    const float* gamma = (const float*)d_in[7];
    float* out = (float*)d_out;

    prep_w<<<640, 128>>>(Wq, bq, Wk, bk, Wv, bv);

    dim3 gx(HW/64, Cc/64, Bn);
    prep_xt<<<gx, 256>>>(x);

    cudaFuncSetAttribute(qkv_gemm_qk, cudaFuncAttributeMaxDynamicSharedMemorySize, SM_QK);
    qkv_gemm_qk<<<dim3(128, Bn), 512, SM_QK>>>();

    cudaFuncSetAttribute(qkv_gemm_v, cudaFuncAttributeMaxDynamicSharedMemorySize, SM_V);
    qkv_gemm_v<<<dim3(4, 128, Bn), 256, SM_V>>>();

    cudaFuncSetAttribute(attn_kernel, cudaFuncAttributeMaxDynamicSharedMemorySize, ATT_SMEM);
    attn_kernel<<<Bn*Hh, 512, ATT_SMEM>>>(x, gamma, out);
}

// round 7
// speedup vs baseline: 4.0919x; 1.0503x over previous
#include <cuda_runtime.h>
#include <cuda_fp16.h>
#include <cstdint>

#define Bn 8
#define Cc 512
#define CQ 64
#define Hh 128
#define Ww 128
#define HW (Hh*Ww)   // 16384

// ---------------------------------------------------------------------------
// Device scratch
// ---------------------------------------------------------------------------
__device__ __half g_v16[(size_t)Bn*Cc*HW];                // [b][c][s] fp16 single
__device__ __half g_xt_hi[(size_t)Bn*HW*Cc];              // xT[b][s][ch]
__device__ __half g_xt_lo[(size_t)Bn*HW*Cc];
__device__ __half g_w_hi[640*Cc];
__device__ __half g_w_lo[640*Cc];
__device__ float g_bias[640];

// ---------------------------------------------------------------------------
// helpers
// ---------------------------------------------------------------------------
__device__ __forceinline__ uint32_t smem_u32(const void* p) {
    uint32_t a;
    asm("{ .reg .u64 t; cvta.to.shared.u64 t, %1; cvt.u32.u64 %0, t; }" : "=r"(a) : "l"(p));
    return a;
}
__device__ __forceinline__ void cp16(uint32_t dst, const void* src) {
    asm volatile("cp.async.cg.shared.global [%0], [%1], 16;" :: "r"(dst), "l"(src));
}
#define CP_COMMIT()      asm volatile("cp.async.commit_group;" ::: "memory")
#define CP_WAIT_GROUP(n) asm volatile("cp.async.wait_group %0;" :: "n"(n) : "memory")

__device__ __forceinline__ void mma_f16(float c[4], uint32_t a0, uint32_t a1, uint32_t a2, uint32_t a3,
                                        uint32_t b0, uint32_t b1) {
    asm volatile("mma.sync.aligned.m16n8k16.row.col.f32.f16.f16.f32 "
                 "{%0,%1,%2,%3}, {%4,%5,%6,%7}, {%8,%9}, {%0,%1,%2,%3};"
                 : "+f"(c[0]), "+f"(c[1]), "+f"(c[2]), "+f"(c[3])
                 : "r"(a0), "r"(a1), "r"(a2), "r"(a3), "r"(b0), "r"(b1));
}
__device__ __forceinline__ void ldsm4(uint32_t& r0, uint32_t& r1, uint32_t& r2, uint32_t& r3,
                                      uint32_t addr) {
    asm volatile("ldmatrix.sync.aligned.m8n8.x4.shared.b16 {%0,%1,%2,%3}, [%4];"
                 : "=r"(r0), "=r"(r1), "=r"(r2), "=r"(r3) : "r"(addr));
}
__device__ __forceinline__ uint32_t prmt(uint32_t a, uint32_t b, uint32_t s) {
    uint32_t d;
    asm("prmt.b32 %0, %1, %2, %3;" : "=r"(d) : "r"(a), "r"(b), "r"(s));
    return d;
}
__device__ __forceinline__ uint32_t pack_hilo(float v) {
    __half h = __float2half_rn(v);
    float r = v - __half2float(h);
    __half l = __float2half_rn(r);
    return (uint32_t)__half_as_ushort(h) | ((uint32_t)__half_as_ushort(l) << 16);
}
__device__ __forceinline__ uint32_t pack2h(float a, float b) {
    __half ha = __float2half_rn(a), hb = __float2half_rn(b);
    return (uint32_t)__half_as_ushort(ha) | ((uint32_t)__half_as_ushort(hb) << 16);
}

// ---------------------------------------------------------------------------
// Prep: W -> fp16 hi/lo (concat rows), bias concat
// ---------------------------------------------------------------------------
__global__ void prep_w(const float* __restrict__ Wq, const float* __restrict__ bq,
                       const float* __restrict__ Wk, const float* __restrict__ bk,
                       const float* __restrict__ Wv, const float* __restrict__ bv)
{
    int r = blockIdx.x;
    const float* src; float bias;
    if (r < 64)       { src = Wq + (size_t)r*Cc;        bias = bq[r]; }
    else if (r < 128) { src = Wk + (size_t)(r-64)*Cc;   bias = bk[r-64]; }
    else              { src = Wv + (size_t)(r-128)*Cc;  bias = bv[r-128]; }
    if (threadIdx.x == 0) g_bias[r] = bias;
    for (int c = threadIdx.x; c < Cc; c += blockDim.x) {
        float v = src[c];
        __half h = __float2half_rn(v);
        g_w_hi[(size_t)r*Cc + c] = h;
        g_w_lo[(size_t)r*Cc + c] = __float2half_rn(v - __half2float(h));
    }
}

// ---------------------------------------------------------------------------
// Prep: x[b][ch][s] -> xT hi/lo [b][s][ch]
// ---------------------------------------------------------------------------
__global__ void __launch_bounds__(256) prep_xt(const float* __restrict__ x)
{
    __shared__ float st[64*65];
    const int b = blockIdx.z, ch0 = blockIdx.y * 64, s0 = blockIdx.x * 64;
    const float* xb = x + ((size_t)b*Cc + ch0)*HW + s0;
    for (int i = threadIdx.x; i < 64*64; i += 256) {
        int ch = i >> 6, s = i & 63;
        st[ch*65 + s] = xb[(size_t)ch*HW + s];
    }
    __syncthreads();
    for (int u = threadIdx.x; u < 512; u += 256) {
        int s = u >> 3, c8 = (u & 7) * 8;
        uint32_t hi[4], lo[4];
        #pragma unroll
        for (int j = 0; j < 4; j++) {
            float a = st[(c8 + 2*j    )*65 + s];
            float c = st[(c8 + 2*j + 1)*65 + s];
            __half ah = __float2half_rn(a), ch_ = __float2half_rn(c);
            __half al = __float2half_rn(a - __half2float(ah));
            __half cl = __float2half_rn(c - __half2float(ch_));
            hi[j] = (uint32_t)__half_as_ushort(ah) | ((uint32_t)__half_as_ushort(ch_) << 16);
            lo[j] = (uint32_t)__half_as_ushort(al) | ((uint32_t)__half_as_ushort(cl) << 16);
        }
        size_t off = ((size_t)(b*HW + s0 + s))*Cc + ch0 + c8;
        *(uint4*)(g_xt_hi + off) = make_uint4(hi[0], hi[1], hi[2], hi[3]);
        *(uint4*)(g_xt_lo + off) = make_uint4(lo[0], lo[1], lo[2], lo[3]);
    }
}

// ---------------------------------------------------------------------------
// V GEMM: rows 128..639 of W, 1-term fp16 (hi only). K chunks of 64,
// 256 threads, 2 CTAs/SM, ldmatrix fragment loads.
// ---------------------------------------------------------------------------
#define V_ROWB 144
#define V_SEG  18432           // 128 rows * 144B
#define STAGE_V (2*V_SEG)      // 36864
#define SM_V (3*STAGE_V)       // 110592

__device__ __forceinline__ void load_chunk_v(uint32_t sb, int tid, int k0, int m0, size_t bofs)
{
    const __half* srcs[2] = {
        g_w_hi + (size_t)(128 + m0)*Cc + k0,
        g_xt_hi + bofs + k0 };
    #pragma unroll
    for (int i = tid; i < 2048; i += 256) {
        int seg = i >> 10;
        int r = (i & 1023) >> 3, u = i & 7;
        cp16(sb + seg*V_SEG + r*V_ROWB + u*16, srcs[seg] + (size_t)r*Cc + u*8);
    }
    CP_COMMIT();
}

__global__ void __launch_bounds__(256, 2) qkv_gemm_v()
{
    extern __shared__ char smem[];
    const uint32_t sbase = smem_u32(smem);
    const int tid = threadIdx.x, wid = tid >> 5, lane = tid & 31;
    const int g = lane >> 2, q = lane & 3;
    const int m0 = blockIdx.x * 128;    // within v rows (0..383)
    const int n0 = blockIdx.y * 128;
    const int b  = blockIdx.z;
    const size_t bofs = ((size_t)b*HW + n0)*Cc;
    const int wm = wid & 1, wn = wid >> 1;
    const int lmat = lane >> 3, lrow = lane & 7;

    float acc[4][4][4];
    #pragma unroll
    for (int i = 0; i < 4; i++)
        #pragma unroll
        for (int j = 0; j < 4; j++)
            #pragma unroll
            for (int e = 0; e < 4; e++) acc[i][j][e] = 0.f;

    load_chunk_v(sbase, tid, 0, m0, bofs);
    load_chunk_v(sbase + STAGE_V, tid, 64, m0, bofs);

    for (int c = 0; c < 8; c++) {
        CP_WAIT_GROUP(1);
        __syncthreads();
        if (c + 2 < 8)
            load_chunk_v(sbase + ((c+2) % 3)*STAGE_V, tid, (c+2)*64, m0, bofs);

        const uint32_t sb = sbase + (c % 3)*STAGE_V;
        #pragma unroll
        for (int ks = 0; ks < 4; ks++) {
            uint32_t ah[4][4], bh[4][2];
            #pragma unroll
            for (int tm = 0; tm < 4; tm++) {
                uint32_t ra = sb + (wm*64 + tm*16 + (lmat&1)*8 + lrow)*V_ROWB + ks*32 + (lmat>>1)*16;
                ldsm4(ah[tm][0], ah[tm][1], ah[tm][2], ah[tm][3], ra);
            }
            #pragma unroll
            for (int tp = 0; tp < 2; tp++) {
                uint32_t rb = sb + V_SEG + (wn*32 + (tp*2 + (lmat>>1))*8 + lrow)*V_ROWB + ks*32 + (lmat&1)*16;
                ldsm4(bh[tp*2][0], bh[tp*2][1], bh[tp*2+1][0], bh[tp*2+1][1], rb);
            }
            #pragma unroll
            for (int tm = 0; tm < 4; tm++)
                #pragma unroll
                for (int tn = 0; tn < 4; tn++)
                    mma_f16(acc[tm][tn], ah[tm][0], ah[tm][1], ah[tm][2], ah[tm][3], bh[tn][0], bh[tn][1]);
        }
        __syncthreads();
    }

    // Epilogue: fp16 single to g_v16[b][c][s]
    #pragma unroll
    for (int tm = 0; tm < 4; tm++) {
        int cv = m0 + wm*64 + tm*16 + g;
        float bias0 = g_bias[128 + cv];
        float bias1 = g_bias[128 + cv + 8];
        #pragma unroll
        for (int tn = 0; tn < 4; tn++) {
            int n = n0 + wn*32 + tn*8 + q*2;
            uint32_t pa = pack2h(acc[tm][tn][0] + bias0, acc[tm][tn][1] + bias0);
            uint32_t pb = pack2h(acc[tm][tn][2] + bias1, acc[tm][tn][3] + bias1);
            *(uint32_t*)&g_v16[((size_t)b*Cc + cv)*HW + n]     = pa;
            *(uint32_t*)&g_v16[((size_t)b*Cc + cv + 8)*HW + n] = pb;
        }
    }
}

// ---------------------------------------------------------------------------
// Fused QK-GEMM + attention kernel. One CTA per (b,h), 512 threads.
// Phase 0: qk GEMM (M=128 [q:0-63,k:64-127], N=128 spatial, K=512, 3-term)
//          -> sq/sk in smem. Phase 1: energy. Phase 2: softmax.
//          Phase 3: out = A @ V in 4 chunks of 128 channels.
// smem map: [0..122880) qk pipeline stages (dead after phase 0)
//           [0..34816) sq (phase0 epi) -> A (after softmax)
//           [34816..69632) sk
//           [69632..137216) E -> ST
//           [137216..206848) v double buffer (2 x 128ch)
// ---------------------------------------------------------------------------
#define ROWB 80
#define SEG  10240
#define STAGE_QK (4*SEG)       // 40960

#define AQK_ROWB 272
#define AA_ROWB  272
#define AV_ROWB  272
#define AE_STRIDE 132
#define AST_STRIDE 132
#define AOFF_Q   0
#define AOFF_K   34816
#define AOFF_A   0
#define AOFF_E   69632
#define AOFF_ST  69632
#define AOFF_V   137216
#define AV_BUFB  34816         // 128 rows * 272
#define ATT_SMEM 206848

__device__ __forceinline__ void load_chunk_qk(uint32_t sb, int tid, int k0, size_t bofs)
{
    const __half* srcs[4] = {
        g_w_hi + k0, g_w_lo + k0,
        g_xt_hi + bofs + k0, g_xt_lo + bofs + k0 };
    #pragma unroll
    for (int i = tid; i < 2048; i += 512) {
        int seg = i >> 9;
        int r = (i & 511) >> 2, u = i & 3;
        cp16(sb + seg*SEG + r*ROWB + u*16, srcs[seg] + (size_t)r*Cc + u*8);
    }
    CP_COMMIT();
}

__device__ __forceinline__ void att_load_v(uint32_t sbv, int tid, int b, int h, int cc)
{
    const __half* src0 = g_v16 + (((size_t)b*Cc + cc)*Hh + h)*Ww;
    #pragma unroll
    for (int i = tid; i < 2048; i += 512) {
        int r = i >> 4, u = i & 15;
        cp16(sbv + r*AV_ROWB + u*16, src0 + (size_t)r*HW + u*8);
    }
    CP_COMMIT();
}

__global__ void __launch_bounds__(512, 1) attn_kernel(
    const float* __restrict__ x,
    const float* __restrict__ gamma_p,
    float* __restrict__ outp)
{
    extern __shared__ char smem[];
    const uint32_t sbase = smem_u32(smem);
    const int tid = threadIdx.x, wid = tid >> 5, lane = tid & 31;
    const int g = lane >> 2, q = lane & 3;
    const int bh = blockIdx.x;
    const int b = bh >> 7, h = bh & 127;
    const float gma = gamma_p[0];
    const size_t bofs = ((size_t)b*HW + h*128)*Cc;
    const int lmat = lane >> 3, lrow = lane & 7;

    // v prefetch (outside stage region) — groups 0,1
    att_load_v(sbase + AOFF_V, tid, b, h, 0);
    att_load_v(sbase + AOFF_V + AV_BUFB, tid, b, h, 128);

    // ======================= Phase 0: QK GEMM ==============================
    {
        const int wm = wid & 3, wn = wid >> 2;   // warp tile 32m x 32n
        float acc[2][4][4];
        #pragma unroll
        for (int i = 0; i < 2; i++)
            #pragma unroll
            for (int j = 0; j < 4; j++)
                #pragma unroll
                for (int e = 0; e < 4; e++) acc[i][j][e] = 0.f;

        load_chunk_qk(sbase, tid, 0, bofs);
        load_chunk_qk(sbase + STAGE_QK, tid, 32, bofs);

        for (int c = 0; c < 16; c++) {
            CP_WAIT_GROUP(1);
            __syncthreads();
            if (c + 2 < 16)
                load_chunk_qk(sbase + ((c+2) % 3)*STAGE_QK, tid, (c+2)*32, bofs);

            const uint32_t sb = sbase + (c % 3)*STAGE_QK;
            #pragma unroll
            for (int ks = 0; ks < 2; ks++) {
                uint32_t ah[2][4], al[2][4], bhf[4][2], blf[4][2];
                #pragma unroll
                for (int tm = 0; tm < 2; tm++) {
                    uint32_t ra = sb + (wm*32 + tm*16 + (lmat&1)*8 + lrow)*ROWB + ks*32 + (lmat>>1)*16;
                    ldsm4(ah[tm][0], ah[tm][1], ah[tm][2], ah[tm][3], ra);
                    ldsm4(al[tm][0], al[tm][1], al[tm][2], al[tm][3], ra + SEG);
                }
                #pragma unroll
                for (int tp = 0; tp < 2; tp++) {
                    uint32_t rb = sb + 2*SEG + (wn*32 + (tp*2 + (lmat>>1))*8 + lrow)*ROWB + ks*32 + (lmat&1)*16;
                    ldsm4(bhf[tp*2][0], bhf[tp*2][1], bhf[tp*2+1][0], bhf[tp*2+1][1], rb);
                    ldsm4(blf[tp*2][0], blf[tp*2][1], blf[tp*2+1][0], blf[tp*2+1][1], rb + SEG);
                }
                #pragma unroll
                for (int tm = 0; tm < 2; tm++)
                    #pragma unroll
                    for (int tn = 0; tn < 4; tn++) {
                        mma_f16(acc[tm][tn], ah[tm][0], ah[tm][1], ah[tm][2], ah[tm][3], bhf[tn][0], bhf[tn][1]);
                        mma_f16(acc[tm][tn], ah[tm][0], ah[tm][1], ah[tm][2], ah[tm][3], blf[tn][0], blf[tn][1]);
                        mma_f16(acc[tm][tn], al[tm][0], al[tm][1], al[tm][2], al[tm][3], bhf[tn][0], bhf[tn][1]);
                    }
            }
            __syncthreads();
        }

        // Epilogue: bias, pack (hi,lo) into smem sq/sk (overlays stages; all
        // mma reads done — last loop iteration ends with __syncthreads()).
        #pragma unroll
        for (int tm = 0; tm < 2; tm++) {
            int mrow = wm*32 + tm*16 + g;
            float bias0 = g_bias[mrow];
            float bias1 = g_bias[mrow + 8];
            #pragma unroll
            for (int tn = 0; tn < 4; tn++) {
                int w = wn*32 + tn*8 + q*2;  // even
                uint32_t p0 = pack_hilo(acc[tm][tn][0] + bias0);
                uint32_t p1 = pack_hilo(acc[tm][tn][1] + bias0);
                uint32_t p2 = pack_hilo(acc[tm][tn][2] + bias1);
                uint32_t p3 = pack_hilo(acc[tm][tn][3] + bias1);
                #pragma unroll
                for (int rr = 0; rr < 2; rr++) {
                    int oc = mrow + rr*8;
                    uint32_t pa = rr ? p2 : p0;
                    uint32_t pb = rr ? p3 : p1;
                    if (oc < 64) {
                        int i = oc*2 + (w >> 6), cc = w & 63;
                        *(uint2*)(smem + AOFF_Q + i*AQK_ROWB + cc*4) = make_uint2(pa, pb);
                    } else {
                        int cq = oc - 64, cc = w >> 1;
                        *(uint32_t*)(smem + AOFF_K + cq*AQK_ROWB + cc*4)        = pa;
                        *(uint32_t*)(smem + AOFF_K + (64 + cq)*AQK_ROWB + cc*4) = pb;
                    }
                }
            }
        }
    }
    __syncthreads();

    const int wi = wid & 3;    // i 32-tile
    const int wj = wid >> 2;   // m 32-cols (energy) / c 32-cols (out)

    // ======================= Phase 1: energy (3-term) ======================
    {
        float e[2][4][4];
        #pragma unroll
        for (int a1 = 0; a1 < 2; a1++)
            #pragma unroll
            for (int a2 = 0; a2 < 4; a2++)
                #pragma unroll
                for (int a3 = 0; a3 < 4; a3++) e[a1][a2][a3] = 0.f;

        #pragma unroll
        for (int ks = 0; ks < 4; ks++) {
            uint32_t ah[2][4], al[2][4], bh_[4][2], bl_[4][2];
            #pragma unroll
            for (int ti = 0; ti < 2; ti++) {
                uint32_t ra = AOFF_Q + (wi*32 + ti*16 + g)*AQK_ROWB + ks*64 + q*8;
                uint2 w00 = *(const uint2*)(smem + ra);
                uint2 w10 = *(const uint2*)(smem + ra + 8*AQK_ROWB);
                uint2 w01 = *(const uint2*)(smem + ra + 32);
                uint2 w11 = *(const uint2*)(smem + ra + 8*AQK_ROWB + 32);
                ah[ti][0] = prmt(w00.x, w00.y, 0x5410); al[ti][0] = prmt(w00.x, w00.y, 0x7632);
                ah[ti][1] = prmt(w10.x, w10.y, 0x5410); al[ti][1] = prmt(w10.x, w10.y, 0x7632);
                ah[ti][2] = prmt(w01.x, w01.y, 0x5410); al[ti][2] = prmt(w01.x, w01.y, 0x7632);
                ah[ti][3] = prmt(w11.x, w11.y, 0x5410); al[ti][3] = prmt(w11.x, w11.y, 0x7632);
            }
            #pragma unroll
            for (int tn = 0; tn < 4; tn++) {
                uint32_t rb = AOFF_K + (wj*32 + tn*8 + g)*AQK_ROWB + ks*64 + q*8;
                uint2 u0 = *(const uint2*)(smem + rb);
                uint2 u1 = *(const uint2*)(smem + rb + 32);
                bh_[tn][0] = prmt(u0.x, u0.y, 0x5410); bl_[tn][0] = prmt(u0.x, u0.y, 0x7632);
                bh_[tn][1] = prmt(u1.x, u1.y, 0x5410); bl_[tn][1] = prmt(u1.x, u1.y, 0x7632);
            }
            #pragma unroll
            for (int ti = 0; ti < 2; ti++)
                #pragma unroll
                for (int tn = 0; tn < 4; tn++) {
                    mma_f16(e[ti][tn], ah[ti][0], ah[ti][1], ah[ti][2], ah[ti][3], bh_[tn][0], bh_[tn][1]);
                    mma_f16(e[ti][tn], al[ti][0], al[ti][1], al[ti][2], al[ti][3], bh_[tn][0], bh_[tn][1]);
                    mma_f16(e[ti][tn], ah[ti][0], ah[ti][1], ah[ti][2], ah[ti][3], bl_[tn][0], bl_[tn][1]);
                }
        }
        float* Ef = (float*)(smem + AOFF_E);
        #pragma unroll
        for (int ti = 0; ti < 2; ti++)
            #pragma unroll
            for (int tn = 0; tn < 4; tn++) {
                int ri = wi*32 + ti*16 + g, cj = wj*32 + tn*8 + 2*q;
                *(float2*)&Ef[ri*AE_STRIDE + cj]     = make_float2(e[ti][tn][0], e[ti][tn][1]);
                *(float2*)&Ef[(ri+8)*AE_STRIDE + cj] = make_float2(e[ti][tn][2], e[ti][tn][3]);
            }
    }
    __syncthreads();

    // ======================= Phase 2: softmax + pack A =====================
    {
        float* Ef = (float*)(smem + AOFF_E);
        int i = tid >> 2, qt = tid & 3;
        float* row = Ef + i*AE_STRIDE + qt*32;
        float mx = -1e30f;
        #pragma unroll 8
        for (int j = 0; j < 32; j++) mx = fmaxf(mx, row[j]);
        mx = fmaxf(mx, __shfl_xor_sync(0xFFFFFFFFu, mx, 1));
        mx = fmaxf(mx, __shfl_xor_sync(0xFFFFFFFFu, mx, 2));
        float s = 0.f;
        #pragma unroll 8
        for (int j = 0; j < 32; j++) { float p = __expf(row[j] - mx); row[j] = p; s += p; }
        s += __shfl_xor_sync(0xFFFFFFFFu, s, 1);
        s += __shfl_xor_sync(0xFFFFFFFFu, s, 2);
        float inv = 1.f / s;
        uint32_t* arow = (uint32_t*)(smem + AOFF_A + i*AA_ROWB + qt*64);
        #pragma unroll 8
        for (int j = 0; j < 32; j += 2)
            arow[j >> 1] = pack2h(row[j]*inv, row[j+1]*inv);
    }
    __syncthreads();

    // ======================= Phase 3: out = A @ V ==========================
    float* STf = (float*)(smem + AOFF_ST);
    for (int ci = 0; ci < 4; ci++) {
        if (ci < 3) { CP_WAIT_GROUP(1); } else { CP_WAIT_GROUP(0); }
        __syncthreads();

        const uint32_t vb = AOFF_V + (ci & 1)*AV_BUFB;
        float o[2][4][4];
        #pragma unroll
        for (int a1 = 0; a1 < 2; a1++)
            #pragma unroll
            for (int a2 = 0; a2 < 4; a2++)
                #pragma unroll
                for (int a3 = 0; a3 < 4; a3++) o[a1][a2][a3] = 0.f;

        #pragma unroll
        for (int ks = 0; ks < 8; ks++) {
            uint32_t a0[2], a1r[2], a2[2], a3[2], b0[4], b1[4];
            #pragma unroll
            for (int ti = 0; ti < 2; ti++) {
                uint32_t ra = AOFF_A + (wi*32 + ti*16 + g)*AA_ROWB + ks*32 + q*4;
                a0[ti]  = *(const uint32_t*)(smem + ra);
                a1r[ti] = *(const uint32_t*)(smem + ra + 8*AA_ROWB);
                a2[ti]  = *(const uint32_t*)(smem + ra + 16);
                a3[ti]  = *(const uint32_t*)(smem + ra + 8*AA_ROWB + 16);
            }
            #pragma unroll
            for (int tn = 0; tn < 4; tn++) {
                uint32_t rb = vb + (wj*32 + tn*8 + g)*AV_ROWB + ks*32 + q*4;
                b0[tn] = *(const uint32_t*)(smem + rb);
                b1[tn] = *(const uint32_t*)(smem + rb + 16);
            }
            #pragma unroll
            for (int ti = 0; ti < 2; ti++)
                #pragma unroll
                for (int tn = 0; tn < 4; tn++)
                    mma_f16(o[ti][tn], a0[ti], a1r[ti], a2[ti], a3[ti], b0[tn], b1[tn]);
        }
        __syncthreads();   // all warps done reading vbuf[ci&1]

        if (ci + 2 < 4) att_load_v(sbase + vb, tid, b, h, (ci+2)*128);

        // stage out[i][c'] -> ST[c'][i]
        #pragma unroll
        for (int ti = 0; ti < 2; ti++)
            #pragma unroll
            for (int tn = 0; tn < 4; tn++) {
                int ri = wi*32 + ti*16 + g, cj = wj*32 + tn*8 + 2*q;
                STf[cj*AST_STRIDE + ri]          = o[ti][tn][0];
                STf[(cj+1)*AST_STRIDE + ri]      = o[ti][tn][1];
                STf[cj*AST_STRIDE + ri + 8]      = o[ti][tn][2];
                STf[(cj+1)*AST_STRIDE + ri + 8]  = o[ti][tn][3];
            }
        __syncthreads();

        // coalesced writeback: out[b][c][h][i] = gma*o + x
        #pragma unroll
        for (int rr = 0; rr < 8; rr++) {
            int r = wid*8 + rr;
            int c = ci*128 + r;
            size_t gofs = (((size_t)b*Cc + c)*Hh + h)*Ww + lane*4;
            float4 xr = *(const float4*)(x + gofs);
            float4 ov = *(const float4*)(STf + r*AST_STRIDE + lane*4);
            *(float4*)(outp + gofs) = make_float4(gma*ov.x + xr.x, gma*ov.y + xr.y,
                                                  gma*ov.z + xr.z, gma*ov.w + xr.w);
        }
    }
}

// ---------------------------------------------------------------------------
extern "C" void kernel_launch(void* const* d_in, const int* in_sizes, int n_in,
                              void* d_out, int out_size)
{
    (void)in_sizes; (void)n_in; (void)out_size;
    const float* x     = (const float*)d_in[0];
    const float* Wq    = (const float*)d_in[1];
    const float* bq    = (const float*)d_in[2];
    const float* Wk    = (const float*)d_in[3];
    const float* bk    = (const float*)d_in[4];
    const float* Wv    = (const float*)d_in[5];
    const float* bv    = (const float*)d_in[6];
    const float* gamma = (const float*)d_in[7];
    float* out = (float*)d_out;

    prep_w<<<640, 128>>>(Wq, bq, Wk, bk, Wv, bv);

    dim3 gx(HW/64, Cc/64, Bn);
    prep_xt<<<gx, 256>>>(x);

    cudaFuncSetAttribute(qkv_gemm_v, cudaFuncAttributeMaxDynamicSharedMemorySize, SM_V);
    qkv_gemm_v<<<dim3(4, 128, Bn), 256, SM_V>>>();

    cudaFuncSetAttribute(attn_kernel, cudaFuncAttributeMaxDynamicSharedMemorySize, ATT_SMEM);
    attn_kernel<<<Bn*Hh, 512, ATT_SMEM>>>(x, gamma, out);
}